// round 11
// baseline (speedup 1.0000x reference)
#include <cuda_runtime.h>
#include <cuda_bf16.h>
#include <math.h>
#include <stdint.h>

#define NB 8
#define NL 1024
#define ND 256
#define NH 8
#define NDH 32
#define NDFF 2048
#define NM (NB*NL)

// ---------------- scratch (device globals; allocation-free, zero-init) ----------------
__device__ __nv_bfloat16 gQhi[64*NL*NDH], gQlo[64*NL*NDH];
__device__ __nv_bfloat16 gKhi[64*NL*NDH], gKlo[64*NL*NDH];
__device__ __nv_bfloat16 gVhi[64*NL*NDH];
__device__ __nv_bfloat16 gSrcHi[NM*ND],  gSrcLo[NM*ND];
__device__ __nv_bfloat16 gCtxHi[NM*ND],  gCtxLo[NM*ND];
__device__ __nv_bfloat16 gHHi[NM*ND],    gHLo[NM*ND];
__device__ __nv_bfloat16 gFFHi[(size_t)NM*NDFF], gFFLo[(size_t)NM*NDFF];
__device__ __nv_bfloat16 gWqkvHi[3*ND*ND], gWqkvLo[3*ND*ND];
__device__ __nv_bfloat16 gWcHi[ND*ND],     gWcLo[ND*ND];
__device__ __nv_bfloat16 gW1Hi[NDFF*ND],   gW1Lo[NDFF*ND];
__device__ __nv_bfloat16 gW2Hi[ND*NDFF],   gW2Lo[ND*NDFF];
__device__ float gBc[ND];
__device__ int   gLen[NB];

// ---------------- helpers ----------------
__device__ __forceinline__ uint32_t smem_u32(const void* p) {
    uint32_t a;
    asm("{ .reg .u64 t; cvta.to.shared.u64 t, %1; cvt.u32.u64 %0, t; }" : "=r"(a) : "l"(p));
    return a;
}
__device__ __forceinline__ void cpasync16(uint32_t saddr, const void* gaddr) {
    asm volatile("cp.async.cg.shared.global [%0], [%1], 16;" :: "r"(saddr), "l"(gaddr) : "memory");
}
#define CP_COMMIT() asm volatile("cp.async.commit_group;" ::: "memory")
#define CP_WAIT(n)  asm volatile("cp.async.wait_group %0;" :: "n"(n) : "memory")

#define LDSM_X4(r0, r1, r2, r3, addr) \
    asm volatile("ldmatrix.sync.aligned.m8n8.x4.shared.b16 {%0,%1,%2,%3}, [%4];" \
        : "=r"(r0), "=r"(r1), "=r"(r2), "=r"(r3) : "r"(addr))
#define LDSM_X4_T(r0, r1, r2, r3, addr) \
    asm volatile("ldmatrix.sync.aligned.m8n8.x4.trans.shared.b16 {%0,%1,%2,%3}, [%4];" \
        : "=r"(r0), "=r"(r1), "=r"(r2), "=r"(r3) : "r"(addr))

#define MMA16816(d, a, b0, b1) \
    asm volatile("mma.sync.aligned.m16n8k16.row.col.f32.bf16.bf16.f32 " \
        "{%0,%1,%2,%3}, {%4,%5,%6,%7}, {%8,%9}, {%0,%1,%2,%3};" \
        : "+f"((d)[0]), "+f"((d)[1]), "+f"((d)[2]), "+f"((d)[3]) \
        : "r"((a)[0]), "r"((a)[1]), "r"((a)[2]), "r"((a)[3]), "r"(b0), "r"(b1))

__device__ __forceinline__ float gelu_f(float x) {
    return 0.5f * x * (1.f + erff(x * 0.7071067811865475f));
}
__device__ __forceinline__ uint32_t pack2_hi(float a, float b) {
    __nv_bfloat16 h0 = __float2bfloat16(a), h1 = __float2bfloat16(b);
    return ((uint32_t)__bfloat16_as_ushort(h1) << 16) | __bfloat16_as_ushort(h0);
}
__device__ __forceinline__ uint32_t pack2_lo(float a, float b) {
    __nv_bfloat16 h0 = __float2bfloat16(a), h1 = __float2bfloat16(b);
    float l0 = a - __bfloat162float(h0), l1 = b - __bfloat162float(h1);
    __nv_bfloat16 g0 = __float2bfloat16(l0), g1 = __float2bfloat16(l1);
    return ((uint32_t)__bfloat16_as_ushort(g1) << 16) | __bfloat16_as_ushort(g0);
}

// ---------------- setup: 8 blocks ----------------
__global__ __launch_bounds__(256) void setup_kernel(const unsigned char* __restrict__ mb) {
    __shared__ int flag, cnt;
    const int b = blockIdx.x, tid = threadIdx.x;
    if (tid == 0) { flag = 0; cnt = 0; }
    __syncthreads();
    int f = 0;
    for (int i = tid; i < NB*NL; i += 256)
        if ((i & 3) != 0 && mb[i] != 0) f = 1;
    if (f) atomicOr(&flag, 1);
    __syncthreads();
    const int mode = flag;
    int c = 0;
    for (int i = tid; i < NL; i += 256) {
        int pad = mode ? (mb[b*NL + i] != 0) : (((const int*)mb)[b*NL + i] != 0);
        if (!pad) c++;
    }
    atomicAdd(&cnt, c);
    __syncthreads();
    if (tid == 0) gLen[b] = cnt;
}

// ---------------- merged fp32 -> bf16 hi/lo conversion ----------------
#define CN0 (NM*ND/4)
#define CN1 (3*ND*ND/4)
#define CN2 (NDFF*ND/4)
#define CN3 (ND*NDFF/4)
__global__ void conv_all(const float* __restrict__ src, const float* __restrict__ w0,
                         const float* __restrict__ w1, const float* __restrict__ w2) {
    int i = blockIdx.x * 256 + threadIdx.x;
    const float* x; __nv_bfloat16 *hi, *lo;
    if (i < CN0)                 { x = src; hi = gSrcHi;  lo = gSrcLo; }
    else if (i < CN0+CN1)        { i -= CN0; x = w0; hi = gWqkvHi; lo = gWqkvLo; }
    else if (i < CN0+CN1+CN2)    { i -= CN0+CN1; x = w1; hi = gW1Hi; lo = gW1Lo; }
    else if (i < CN0+CN1+CN2+CN3){ i -= CN0+CN1+CN2; x = w2; hi = gW2Hi; lo = gW2Lo; }
    else return;
    float4 f = ((const float4*)x)[i];
    uint2 h, l;
    h.x = pack2_hi(f.x, f.y); h.y = pack2_hi(f.z, f.w);
    l.x = pack2_lo(f.x, f.y); l.y = pack2_lo(f.z, f.w);
    ((uint2*)hi)[i] = h;
    ((uint2*)lo)[i] = l;
}

// ---------------- merged weight+bias fusion ----------------
__global__ void fuse_wb(const float* __restrict__ pw, const float* __restrict__ ow,
                        const float* __restrict__ ob, const float* __restrict__ pb) {
    int i = blockIdx.x, j = threadIdx.x;
    if (i == ND) {
        float s = pb[j];
        #pragma unroll 8
        for (int k = 0; k < ND; k++)
            s = fmaf(pw[j*ND + k], ob[k], s);
        gBc[j] = s;
        return;
    }
    float s = 0.f;
    #pragma unroll 8
    for (int k = 0; k < ND; k++)
        s = fmaf(pw[i*ND + k], ow[k*ND + j], s);
    __nv_bfloat16 h = __float2bfloat16(s);
    gWcHi[i*ND + j] = h;
    gWcLo[i*ND + j] = __float2bfloat16(s - __bfloat162float(h));
}

// ---------------- mma.sync split-bf16 GEMM (R10 winner — unchanged) ----------------
#define ATILE (128*80)
#define STAGE_B (4*ATILE)
#define SMEM_DYN (2*STAGE_B)      // 81920

template<int EPI>
__global__ __launch_bounds__(256, 2) void mma_gemm(
    const __nv_bfloat16* __restrict__ Ahi, const __nv_bfloat16* __restrict__ Alo,
    const __nv_bfloat16* __restrict__ Bhi, const __nv_bfloat16* __restrict__ Blo,
    const float* __restrict__ bias,
    float* __restrict__ Cf, __nv_bfloat16* __restrict__ Chi, __nv_bfloat16* __restrict__ Clo,
    const float* __restrict__ resf, int M, int N, int K)
{
    extern __shared__ char sm[];
    const uint32_t sb = smem_u32(sm);
    const int tid = threadIdx.x;
    const int lane = tid & 31, wid = tid >> 5;
    const int wm = wid & 3, wn = wid >> 2;
    const int bm = blockIdx.y * 128, bn = blockIdx.x * 128;

    if ((bm & (NL - 1)) >= gLen[bm >> 10]) {
        if (EPI == 3) {
            const float4 z4 = make_float4(0.f, 0.f, 0.f, 0.f);
            #pragma unroll
            for (int it = 0; it < 16; it++) {
                int u = it * 256 + tid;
                int r = u >> 5, c = (u & 31) << 2;
                *(float4*)(Cf + (size_t)(bm + r) * N + bn + c) = z4;
            }
        }
        return;
    }

    float acc[2][8][4];
    #pragma unroll
    for (int i = 0; i < 2; i++)
        #pragma unroll
        for (int j = 0; j < 8; j++)
            #pragma unroll
            for (int c = 0; c < 4; c++) acc[i][j][c] = 0.f;

    const int nt = K >> 5;

    auto prefetch = [&](int stage, int kt) {
        const int k0 = kt << 5;
        #pragma unroll
        for (int it = 0; it < 8; it++) {
            int u = (it << 8) + tid;
            int mat = u >> 9, w = u & 511, r = w >> 2, c = w & 3;
            const __nv_bfloat16* g;
            int rb;
            if      (mat == 0) { g = Ahi; rb = bm; }
            else if (mat == 1) { g = Alo; rb = bm; }
            else if (mat == 2) { g = Bhi; rb = bn; }
            else               { g = Blo; rb = bn; }
            cpasync16(sb + (uint32_t)(stage * STAGE_B + mat * ATILE + r * 80 + (c << 4)),
                      g + (size_t)(rb + r) * K + k0 + (c << 3));
        }
        CP_COMMIT();
    };

    auto compute = [&](int stage) {
        const uint32_t stb = sb + (uint32_t)(stage * STAGE_B);
        const int g = lane >> 3;
        #pragma unroll
        for (int ks = 0; ks < 2; ks++) {
            uint32_t af[2][2][4];
            #pragma unroll
            for (int d = 0; d < 2; d++)
                #pragma unroll
                for (int fm = 0; fm < 2; fm++) {
                    int row = wm * 32 + fm * 16 + (lane & 15);
                    int chunk = ks * 2 + (lane >> 4);
                    uint32_t a = stb + (uint32_t)(d * ATILE + row * 80 + chunk * 16);
                    LDSM_X4(af[d][fm][0], af[d][fm][1], af[d][fm][2], af[d][fm][3], a);
                }
            uint32_t bf_[4][4];
            #pragma unroll
            for (int fq = 0; fq < 4; fq++) {
                int row = wn * 64 + fq * 16 + ((g >> 1) << 3) + (lane & 7);
                int chunk = ks * 2 + (g & 1);
                uint32_t a = stb + (uint32_t)(2 * ATILE + row * 80 + chunk * 16);
                LDSM_X4(bf_[fq][0], bf_[fq][1], bf_[fq][2], bf_[fq][3], a);
            }
            #pragma unroll
            for (int fm = 0; fm < 2; fm++)
                #pragma unroll
                for (int fn = 0; fn < 8; fn++) {
                    uint32_t b0 = bf_[fn >> 1][(fn & 1) * 2], b1 = bf_[fn >> 1][(fn & 1) * 2 + 1];
                    MMA16816(acc[fm][fn], af[0][fm], b0, b1);
                    MMA16816(acc[fm][fn], af[1][fm], b0, b1);
                }
            #pragma unroll
            for (int fq = 0; fq < 4; fq++) {
                int row = wn * 64 + fq * 16 + ((g >> 1) << 3) + (lane & 7);
                int chunk = ks * 2 + (g & 1);
                uint32_t a = stb + (uint32_t)(3 * ATILE + row * 80 + chunk * 16);
                LDSM_X4(bf_[fq][0], bf_[fq][1], bf_[fq][2], bf_[fq][3], a);
            }
            #pragma unroll
            for (int fm = 0; fm < 2; fm++)
                #pragma unroll
                for (int fn = 0; fn < 8; fn++) {
                    uint32_t b0 = bf_[fn >> 1][(fn & 1) * 2], b1 = bf_[fn >> 1][(fn & 1) * 2 + 1];
                    MMA16816(acc[fm][fn], af[0][fm], b0, b1);
                }
        }
    };

    prefetch(0, 0);
    for (int i = 0; i < nt; i++) {
        CP_WAIT(0);
        __syncthreads();
        if (i + 1 < nt) prefetch((i + 1) & 1, i + 1);
        compute(i & 1);
    }

    const int tq = lane >> 2, tr2 = (lane & 3) << 1;
    #pragma unroll
    for (int fm = 0; fm < 2; fm++) {
        #pragma unroll
        for (int fn = 0; fn < 8; fn++) {
            int col = bn + wn * 64 + fn * 8 + tr2;
            float b0 = __ldg(bias + col), b1 = __ldg(bias + col + 1);
            #pragma unroll
            for (int half = 0; half < 2; half++) {
                int row = bm + wm * 32 + fm * 16 + tq + half * 8;
                float v0 = acc[fm][fn][half * 2]     + b0;
                float v1 = acc[fm][fn][half * 2 + 1] + b1;
                if (EPI == 0) {
                    int t = col >> 8, h = (col & 255) >> 5, dh = col & 31;
                    int bb = row >> 10, ll = row & 1023;
                    size_t o = (((size_t)(bb * NH + h)) * NL + ll) * NDH + dh;
                    uint32_t hv = pack2_hi(v0, v1), lv = pack2_lo(v0, v1);
                    if (t == 0)      { *(uint32_t*)(gQhi + o) = hv; *(uint32_t*)(gQlo + o) = lv; }
                    else if (t == 1) { *(uint32_t*)(gKhi + o) = hv; *(uint32_t*)(gKlo + o) = lv; }
                    else             { *(uint32_t*)(gVhi + o) = hv; }
                } else if (EPI == 1) {
                    size_t o = (size_t)row * N + col;
                    v0 += __ldg(resf + o); v1 += __ldg(resf + o + 1);
                    *(uint32_t*)(Chi + o) = pack2_hi(v0, v1);
                    *(uint32_t*)(Clo + o) = pack2_lo(v0, v1);
                } else if (EPI == 2) {
                    size_t o = (size_t)row * N + col;
                    v0 = gelu_f(v0); v1 = gelu_f(v1);
                    *(uint32_t*)(Chi + o) = pack2_hi(v0, v1);
                    *(uint32_t*)(Clo + o) = pack2_lo(v0, v1);
                } else {
                    size_t o = (size_t)row * N + col;
                    uint32_t rh = *(const uint32_t*)(Chi + o);
                    uint32_t rl = *(const uint32_t*)(Clo + o);
                    v0 += __bfloat162float(__ushort_as_bfloat16((unsigned short)(rh & 0xffff)))
                        + __bfloat162float(__ushort_as_bfloat16((unsigned short)(rl & 0xffff)));
                    v1 += __bfloat162float(__ushort_as_bfloat16((unsigned short)(rh >> 16)))
                        + __bfloat162float(__ushort_as_bfloat16((unsigned short)(rl >> 16)));
                    int bb = row >> 10, ll = row & 1023;
                    if (ll >= gLen[bb]) { v0 = 0.f; v1 = 0.f; }
                    *(float2*)(Cf + o) = make_float2(v0, v1);
                }
            }
        }
    }
}

// ---------------- tensor-core flash attention: 128-key tiles, log2 softmax ----------
#define AQ_B 5120                 // 64 q rows x 80B
#define AKV_B (3*128*80)          // Khi,Klo,Vhi: 128 rows x 80B each = 30720
#define SMEM_ATT (2*AQ_B + 2*AKV_B)  // 71680

__global__ __launch_bounds__(128) void attn_mma_kernel() {
    extern __shared__ __align__(16) unsigned char smem[];
    const uint32_t sb = smem_u32(smem);
    const uint32_t sQhi = sb, sQlo = sb + AQ_B;
    const uint32_t sKV0 = sb + 2*AQ_B;

    const int tid = threadIdx.x, lane = tid & 31, wq = tid >> 5;
    const int bh = blockIdx.y, b = bh >> 3, h = bh & 7;
    const int qbase = blockIdx.x * 64;
    const int g = lane >> 3;
    const int tq = lane >> 2, tt = lane & 3;

    const int S = gLen[b];
    if (qbase >= S) return;

    const __nv_bfloat16* Qh = gQhi + (size_t)bh * NL * NDH;
    const __nv_bfloat16* Ql = gQlo + (size_t)bh * NL * NDH;
    const __nv_bfloat16* Kh = gKhi + (size_t)bh * NL * NDH;
    const __nv_bfloat16* Kl = gKlo + (size_t)bh * NL * NDH;
    const __nv_bfloat16* Vh = gVhi + (size_t)bh * NL * NDH;

    const float LOG2E = 1.4426950408889634f;
    const float sf = (float)S;
    const float invs_l2 = LOG2E / sf;
    const float scale_l2 = 0.1767766952966369f * LOG2E;
    const float sfl2 = LOG2E;          // (sf - dist)/sf * LOG2E = LOG2E - dist*invs_l2
    const int nt = (S + 127) >> 7;     // 128-key tiles

    // stage Q (hi+lo)
    #pragma unroll
    for (int it = 0; it < 4; it++) {
        int u = (it << 7) + tid;
        int mat = u >> 8, w = u & 255, r = w >> 2, c = w & 3;
        const __nv_bfloat16* gp = mat ? Ql : Qh;
        cpasync16((mat ? sQlo : sQhi) + (uint32_t)(r * 80 + (c << 4)),
                  gp + (size_t)(qbase + r) * NDH + (c << 3));
    }
    auto loadKV = [&](int stage, int kt) {
        uint32_t base = sKV0 + (uint32_t)stage * AKV_B;
        #pragma unroll
        for (int it = 0; it < 12; it++) {
            int u = (it << 7) + tid;       // 0..1535
            int mat = u >> 9, w = u & 511, r = w >> 2, c = w & 3;
            const __nv_bfloat16* gp = (mat == 0) ? Kh : (mat == 1) ? Kl : Vh;
            cpasync16(base + (uint32_t)(mat * (128*80) + r * 80 + (c << 4)),
                      gp + (size_t)(kt + r) * NDH + (c << 3));
        }
        CP_COMMIT();
    };
    loadKV(0, 0);

    uint32_t aQh[2][4], aQl[2][4];
    float oAcc[4][4];
    #pragma unroll
    for (int i = 0; i < 4; i++)
        #pragma unroll
        for (int j = 0; j < 4; j++) oAcc[i][j] = 0.f;
    float mrow0 = -1e30f, mrow1 = -1e30f, lp0 = 0.f, lp1 = 0.f;

    const float qr0 = (float)(qbase + wq * 16 + tq);
    const float qr1 = qr0 + 8.f;

    for (int i = 0; i < nt; i++) {
        if (i + 1 < nt) { loadKV((i + 1) & 1, (i + 1) << 7); CP_WAIT(1); }
        else            { CP_WAIT(0); }
        __syncthreads();

        if (i == 0) {
            #pragma unroll
            for (int ks = 0; ks < 2; ks++) {
                uint32_t roff = (uint32_t)((wq * 16 + ((g & 1) << 3) + (lane & 7)) * 80
                                           + 32 * ks + 16 * (g >> 1));
                LDSM_X4(aQh[ks][0], aQh[ks][1], aQh[ks][2], aQh[ks][3], sQhi + roff);
                LDSM_X4(aQl[ks][0], aQl[ks][1], aQl[ks][2], aQl[ks][3], sQlo + roff);
            }
        }

        const uint32_t sT  = sKV0 + (uint32_t)(i & 1) * AKV_B;

        #pragma unroll
        for (int hk = 0; hk < 2; hk++) {
            const int kt = (i << 7) + hk * 64;
            if (kt >= S) break;
            const uint32_t sK  = sT + (uint32_t)(hk * 64 * 80);
            const uint32_t sKl = sK + 128*80;
            const uint32_t sV  = sK + 2*128*80;

            float sA[8][4];
            #pragma unroll
            for (int j = 0; j < 8; j++)
                #pragma unroll
                for (int c = 0; c < 4; c++) sA[j][c] = 0.f;

            #pragma unroll
            for (int ks = 0; ks < 2; ks++) {
                #pragma unroll
                for (int jp = 0; jp < 4; jp++) {
                    uint32_t kh[4], kl[4];
                    uint32_t roff = (uint32_t)((16 * jp + ((g >> 1) << 3) + (lane & 7)) * 80
                                               + 32 * ks + 16 * (g & 1));
                    LDSM_X4(kh[0], kh[1], kh[2], kh[3], sK + roff);
                    LDSM_X4(kl[0], kl[1], kl[2], kl[3], sKl + roff);
                    MMA16816(sA[2*jp],     aQh[ks], kh[0], kh[1]);
                    MMA16816(sA[2*jp],     aQl[ks], kh[0], kh[1]);
                    MMA16816(sA[2*jp],     aQh[ks], kl[0], kl[1]);
                    MMA16816(sA[2*jp + 1], aQh[ks], kh[2], kh[3]);
                    MMA16816(sA[2*jp + 1], aQl[ks], kh[2], kh[3]);
                    MMA16816(sA[2*jp + 1], aQh[ks], kl[2], kl[3]);
                }
            }

            // log2-domain bias + online softmax
            float x[8][4];
            float tmax0 = -1e30f, tmax1 = -1e30f;
            #pragma unroll
            for (int j = 0; j < 8; j++) {
                int kc = kt + 8 * j + 2 * tt;
                float k0f = (float)kc, k1f = k0f + 1.f;
                float b00 = (kc     < S) ? sfl2 - fabsf(qr0 - k0f) * invs_l2 : -1e30f;
                float b01 = (kc + 1 < S) ? sfl2 - fabsf(qr0 - k1f) * invs_l2 : -1e30f;
                float b10 = (kc     < S) ? sfl2 - fabsf(qr1 - k0f) * invs_l2 : -1e30f;
                float b11 = (kc + 1 < S) ? sfl2 - fabsf(qr1 - k1f) * invs_l2 : -1e30f;
                x[j][0] = fmaf(sA[j][0], scale_l2, b00);
                x[j][1] = fmaf(sA[j][1], scale_l2, b01);
                x[j][2] = fmaf(sA[j][2], scale_l2, b10);
                x[j][3] = fmaf(sA[j][3], scale_l2, b11);
                tmax0 = fmaxf(tmax0, fmaxf(x[j][0], x[j][1]));
                tmax1 = fmaxf(tmax1, fmaxf(x[j][2], x[j][3]));
            }
            tmax0 = fmaxf(tmax0, __shfl_xor_sync(0xffffffff, tmax0, 1));
            tmax0 = fmaxf(tmax0, __shfl_xor_sync(0xffffffff, tmax0, 2));
            tmax1 = fmaxf(tmax1, __shfl_xor_sync(0xffffffff, tmax1, 1));
            tmax1 = fmaxf(tmax1, __shfl_xor_sync(0xffffffff, tmax1, 2));
            float mn0 = fmaxf(mrow0, tmax0), mn1 = fmaxf(mrow1, tmax1);
            float corr0 = exp2f(mrow0 - mn0), corr1 = exp2f(mrow1 - mn1);
            mrow0 = mn0; mrow1 = mn1;
            lp0 *= corr0; lp1 *= corr1;
            #pragma unroll
            for (int nf = 0; nf < 4; nf++) {
                oAcc[nf][0] *= corr0; oAcc[nf][1] *= corr0;
                oAcc[nf][2] *= corr1; oAcc[nf][3] *= corr1;
            }

            uint32_t aP[4][4];
            #pragma unroll
            for (int j = 0; j < 8; j++) {
                float p0 = exp2f(x[j][0] - mn0), p1 = exp2f(x[j][1] - mn0);
                float p2 = exp2f(x[j][2] - mn1), p3 = exp2f(x[j][3] - mn1);
                lp0 += p0 + p1; lp1 += p2 + p3;
                int jp = j >> 1, s2 = (j & 1) << 1;
                aP[jp][s2]     = pack2_hi(p0, p1);
                aP[jp][s2 + 1] = pack2_hi(p2, p3);
            }

            #pragma unroll
            for (int jp = 0; jp < 4; jp++) {
                uint32_t bv[8];
                uint32_t roff = (uint32_t)((16 * jp + ((g & 1) << 3) + (lane & 7)) * 80
                                           + 16 * (g >> 1));
                LDSM_X4_T(bv[0], bv[1], bv[2], bv[3], sV + roff);
                LDSM_X4_T(bv[4], bv[5], bv[6], bv[7], sV + roff + 32);
                MMA16816(oAcc[0], aP[jp], bv[0], bv[1]);
                MMA16816(oAcc[1], aP[jp], bv[2], bv[3]);
                MMA16816(oAcc[2], aP[jp], bv[4], bv[5]);
                MMA16816(oAcc[3], aP[jp], bv[6], bv[7]);
            }
        }
        __syncthreads();
    }

    lp0 += __shfl_xor_sync(0xffffffff, lp0, 1);
    lp0 += __shfl_xor_sync(0xffffffff, lp0, 2);
    lp1 += __shfl_xor_sync(0xffffffff, lp1, 1);
    lp1 += __shfl_xor_sync(0xffffffff, lp1, 2);
    float inv0 = 1.f / lp0, inv1 = 1.f / lp1;
    int r0 = qbase + wq * 16 + tq, r1 = r0 + 8;
    #pragma unroll
    for (int nf = 0; nf < 4; nf++) {
        int dh = 8 * nf + 2 * tt;
        size_t o0 = ((size_t)(b * NL + r0)) * ND + h * NDH + dh;
        size_t o1 = ((size_t)(b * NL + r1)) * ND + h * NDH + dh;
        float v00 = oAcc[nf][0] * inv0, v01 = oAcc[nf][1] * inv0;
        float v10 = oAcc[nf][2] * inv1, v11 = oAcc[nf][3] * inv1;
        *(uint32_t*)(gCtxHi + o0) = pack2_hi(v00, v01);
        *(uint32_t*)(gCtxLo + o0) = pack2_lo(v00, v01);
        *(uint32_t*)(gCtxHi + o1) = pack2_hi(v10, v11);
        *(uint32_t*)(gCtxLo + o1) = pack2_lo(v10, v11);
    }
}

// ---------------- launcher ----------------
extern "C" void kernel_launch(void* const* d_in, const int* in_sizes, int n_in,
                              void* d_out, int out_size) {
    const float* src       = (const float*)d_in[0];
    const unsigned char* mask = (const unsigned char*)d_in[1];
    const float* in_proj_w = (const float*)d_in[2];
    const float* in_proj_b = (const float*)d_in[3];
    const float* out_w     = (const float*)d_in[4];
    const float* out_b     = (const float*)d_in[5];
    const float* proj_w    = (const float*)d_in[6];
    const float* proj_b    = (const float*)d_in[7];
    const float* ff1_w     = (const float*)d_in[8];
    const float* ff1_b     = (const float*)d_in[9];
    const float* ff2_w     = (const float*)d_in[10];
    const float* ff2_b     = (const float*)d_in[11];
    float* out = (float*)d_out;

    cudaFuncSetAttribute(mma_gemm<0>, cudaFuncAttributeMaxDynamicSharedMemorySize, SMEM_DYN);
    cudaFuncSetAttribute(mma_gemm<1>, cudaFuncAttributeMaxDynamicSharedMemorySize, SMEM_DYN);
    cudaFuncSetAttribute(mma_gemm<2>, cudaFuncAttributeMaxDynamicSharedMemorySize, SMEM_DYN);
    cudaFuncSetAttribute(mma_gemm<3>, cudaFuncAttributeMaxDynamicSharedMemorySize, SMEM_DYN);
    cudaFuncSetAttribute(attn_mma_kernel, cudaFuncAttributeMaxDynamicSharedMemorySize, SMEM_ATT);

    float *pBc;
    __nv_bfloat16 *pSrcHi, *pSrcLo, *pCtxHi, *pCtxLo, *pHHi, *pHLo, *pFFHi, *pFFLo;
    __nv_bfloat16 *pWqkvHi, *pWqkvLo, *pWcHi, *pWcLo, *pW1Hi, *pW1Lo, *pW2Hi, *pW2Lo;
    cudaGetSymbolAddress((void**)&pBc, gBc);
    cudaGetSymbolAddress((void**)&pSrcHi, gSrcHi);  cudaGetSymbolAddress((void**)&pSrcLo, gSrcLo);
    cudaGetSymbolAddress((void**)&pCtxHi, gCtxHi);  cudaGetSymbolAddress((void**)&pCtxLo, gCtxLo);
    cudaGetSymbolAddress((void**)&pHHi, gHHi);      cudaGetSymbolAddress((void**)&pHLo, gHLo);
    cudaGetSymbolAddress((void**)&pFFHi, gFFHi);    cudaGetSymbolAddress((void**)&pFFLo, gFFLo);
    cudaGetSymbolAddress((void**)&pWqkvHi, gWqkvHi); cudaGetSymbolAddress((void**)&pWqkvLo, gWqkvLo);
    cudaGetSymbolAddress((void**)&pWcHi, gWcHi);    cudaGetSymbolAddress((void**)&pWcLo, gWcLo);
    cudaGetSymbolAddress((void**)&pW1Hi, gW1Hi);    cudaGetSymbolAddress((void**)&pW1Lo, gW1Lo);
    cudaGetSymbolAddress((void**)&pW2Hi, gW2Hi);    cudaGetSymbolAddress((void**)&pW2Lo, gW2Lo);

    setup_kernel<<<NB, 256>>>(mask);
    conv_all<<<(CN0+CN1+CN2+CN3 + 255)/256, 256>>>(src, in_proj_w, ff1_w, ff2_w);
    fuse_wb<<<ND + 1, ND>>>(proj_w, out_w, out_b, proj_b);

    // QKV = src @ in_proj_w^T + b -> bf16 Q/K/V (hi/lo)
    mma_gemm<0><<<dim3(6, 64), 256, SMEM_DYN>>>(pSrcHi, pSrcLo, pWqkvHi, pWqkvLo,
        in_proj_b, nullptr, nullptr, nullptr, nullptr, NM, 3*ND, ND);
    // tensor-core attention -> ctx hi/lo
    attn_mma_kernel<<<dim3(16, 64), 128, SMEM_ATT>>>();
    // H = src + ctx @ Wc^T + bc -> hi/lo only
    mma_gemm<1><<<dim3(2, 64), 256, SMEM_DYN>>>(pCtxHi, pCtxLo, pWcHi, pWcLo,
        pBc, nullptr, pHHi, pHLo, src, NM, ND, ND);
    // ff = gelu(H @ ff1_w^T + b1) -> hi/lo
    mma_gemm<2><<<dim3(16, 64), 256, SMEM_DYN>>>(pHHi, pHLo, pW1Hi, pW1Lo,
        ff1_b, nullptr, pFFHi, pFFLo, nullptr, NM, NDFF, ND);
    // out = (Hhi+Hlo) + ff @ ff2_w^T + b2, padded rows zeroed
    mma_gemm<3><<<dim3(2, 64), 256, SMEM_DYN>>>(pFFHi, pFFLo, pW2Hi, pW2Lo,
        ff2_b, out, pHHi, pHLo, nullptr, NM, ND, NDFF);
}

// round 12
// speedup vs baseline: 1.0692x; 1.0692x over previous
#include <cuda_runtime.h>
#include <cuda_bf16.h>
#include <math.h>
#include <stdint.h>

#define NB 8
#define NL 1024
#define ND 256
#define NH 8
#define NDH 32
#define NDFF 2048
#define NM (NB*NL)

// ---------------- scratch (device globals; allocation-free, zero-init) ----------------
__device__ __nv_bfloat16 gQhi[64*NL*NDH];
__device__ __nv_bfloat16 gKhi[64*NL*NDH];
__device__ __nv_bfloat16 gVhi[64*NL*NDH];
__device__ __nv_bfloat16 gSrcHi[NM*ND],  gSrcLo[NM*ND];
__device__ __nv_bfloat16 gCtxHi[NM*ND],  gCtxLo[NM*ND];
__device__ __nv_bfloat16 gHHi[NM*ND],    gHLo[NM*ND];
__device__ __nv_bfloat16 gFFHi[(size_t)NM*NDFF], gFFLo[(size_t)NM*NDFF];
__device__ __nv_bfloat16 gWqkvHi[3*ND*ND], gWqkvLo[3*ND*ND];
__device__ __nv_bfloat16 gWcHi[ND*ND],     gWcLo[ND*ND];
__device__ __nv_bfloat16 gW1Hi[NDFF*ND],   gW1Lo[NDFF*ND];
__device__ __nv_bfloat16 gW2Hi[ND*NDFF],   gW2Lo[ND*NDFF];
__device__ float gBc[ND];
__device__ int   gLen[NB];

// ---------------- helpers ----------------
__device__ __forceinline__ uint32_t smem_u32(const void* p) {
    uint32_t a;
    asm("{ .reg .u64 t; cvta.to.shared.u64 t, %1; cvt.u32.u64 %0, t; }" : "=r"(a) : "l"(p));
    return a;
}
__device__ __forceinline__ void cpasync16(uint32_t saddr, const void* gaddr) {
    asm volatile("cp.async.cg.shared.global [%0], [%1], 16;" :: "r"(saddr), "l"(gaddr) : "memory");
}
#define CP_COMMIT() asm volatile("cp.async.commit_group;" ::: "memory")
#define CP_WAIT(n)  asm volatile("cp.async.wait_group %0;" :: "n"(n) : "memory")

#define LDSM_X4(r0, r1, r2, r3, addr) \
    asm volatile("ldmatrix.sync.aligned.m8n8.x4.shared.b16 {%0,%1,%2,%3}, [%4];" \
        : "=r"(r0), "=r"(r1), "=r"(r2), "=r"(r3) : "r"(addr))
#define LDSM_X4_T(r0, r1, r2, r3, addr) \
    asm volatile("ldmatrix.sync.aligned.m8n8.x4.trans.shared.b16 {%0,%1,%2,%3}, [%4];" \
        : "=r"(r0), "=r"(r1), "=r"(r2), "=r"(r3) : "r"(addr))

#define MMA16816(d, a, b0, b1) \
    asm volatile("mma.sync.aligned.m16n8k16.row.col.f32.bf16.bf16.f32 " \
        "{%0,%1,%2,%3}, {%4,%5,%6,%7}, {%8,%9}, {%0,%1,%2,%3};" \
        : "+f"((d)[0]), "+f"((d)[1]), "+f"((d)[2]), "+f"((d)[3]) \
        : "r"((a)[0]), "r"((a)[1]), "r"((a)[2]), "r"((a)[3]), "r"(b0), "r"(b1))

__device__ __forceinline__ float gelu_f(float x) {
    return 0.5f * x * (1.f + erff(x * 0.7071067811865475f));
}
__device__ __forceinline__ uint32_t pack2_hi(float a, float b) {
    __nv_bfloat16 h0 = __float2bfloat16(a), h1 = __float2bfloat16(b);
    return ((uint32_t)__bfloat16_as_ushort(h1) << 16) | __bfloat16_as_ushort(h0);
}
__device__ __forceinline__ uint32_t pack2_lo(float a, float b) {
    __nv_bfloat16 h0 = __float2bfloat16(a), h1 = __float2bfloat16(b);
    float l0 = a - __bfloat162float(h0), l1 = b - __bfloat162float(h1);
    __nv_bfloat16 g0 = __float2bfloat16(l0), g1 = __float2bfloat16(l1);
    return ((uint32_t)__bfloat16_as_ushort(g1) << 16) | __bfloat16_as_ushort(g0);
}

// ---------------- setup: 8 blocks ----------------
__global__ __launch_bounds__(256) void setup_kernel(const unsigned char* __restrict__ mb) {
    __shared__ int flag, cnt;
    const int b = blockIdx.x, tid = threadIdx.x;
    if (tid == 0) { flag = 0; cnt = 0; }
    __syncthreads();
    int f = 0;
    for (int i = tid; i < NB*NL; i += 256)
        if ((i & 3) != 0 && mb[i] != 0) f = 1;
    if (f) atomicOr(&flag, 1);
    __syncthreads();
    const int mode = flag;
    int c = 0;
    for (int i = tid; i < NL; i += 256) {
        int pad = mode ? (mb[b*NL + i] != 0) : (((const int*)mb)[b*NL + i] != 0);
        if (!pad) c++;
    }
    atomicAdd(&cnt, c);
    __syncthreads();
    if (tid == 0) gLen[b] = cnt;
}

// ---------------- merged fp32 -> bf16 hi/lo conversion ----------------
#define CN0 (NM*ND/4)
#define CN1 (3*ND*ND/4)
#define CN2 (NDFF*ND/4)
#define CN3 (ND*NDFF/4)
__global__ void conv_all(const float* __restrict__ src, const float* __restrict__ w0,
                         const float* __restrict__ w1, const float* __restrict__ w2) {
    int i = blockIdx.x * 256 + threadIdx.x;
    const float* x; __nv_bfloat16 *hi, *lo;
    if (i < CN0)                 { x = src; hi = gSrcHi;  lo = gSrcLo; }
    else if (i < CN0+CN1)        { i -= CN0; x = w0; hi = gWqkvHi; lo = gWqkvLo; }
    else if (i < CN0+CN1+CN2)    { i -= CN0+CN1; x = w1; hi = gW1Hi; lo = gW1Lo; }
    else if (i < CN0+CN1+CN2+CN3){ i -= CN0+CN1+CN2; x = w2; hi = gW2Hi; lo = gW2Lo; }
    else return;
    float4 f = ((const float4*)x)[i];
    uint2 h, l;
    h.x = pack2_hi(f.x, f.y); h.y = pack2_hi(f.z, f.w);
    l.x = pack2_lo(f.x, f.y); l.y = pack2_lo(f.z, f.w);
    ((uint2*)hi)[i] = h;
    ((uint2*)lo)[i] = l;
}

// ---------------- merged weight+bias fusion ----------------
__global__ void fuse_wb(const float* __restrict__ pw, const float* __restrict__ ow,
                        const float* __restrict__ ob, const float* __restrict__ pb) {
    int i = blockIdx.x, j = threadIdx.x;
    if (i == ND) {
        float s = pb[j];
        #pragma unroll 8
        for (int k = 0; k < ND; k++)
            s = fmaf(pw[j*ND + k], ob[k], s);
        gBc[j] = s;
        return;
    }
    float s = 0.f;
    #pragma unroll 8
    for (int k = 0; k < ND; k++)
        s = fmaf(pw[i*ND + k], ow[k*ND + j], s);
    __nv_bfloat16 h = __float2bfloat16(s);
    gWcHi[i*ND + j] = h;
    gWcLo[i*ND + j] = __float2bfloat16(s - __bfloat162float(h));
}

// ---------------- mma.sync split-bf16 GEMM (R10 winner — unchanged) ----------------
#define ATILE (128*80)
#define STAGE_B (4*ATILE)
#define SMEM_DYN (2*STAGE_B)      // 81920

template<int EPI>
__global__ __launch_bounds__(256, 2) void mma_gemm(
    const __nv_bfloat16* __restrict__ Ahi, const __nv_bfloat16* __restrict__ Alo,
    const __nv_bfloat16* __restrict__ Bhi, const __nv_bfloat16* __restrict__ Blo,
    const float* __restrict__ bias,
    float* __restrict__ Cf, __nv_bfloat16* __restrict__ Chi, __nv_bfloat16* __restrict__ Clo,
    const float* __restrict__ resf, int M, int N, int K)
{
    extern __shared__ char sm[];
    const uint32_t sb = smem_u32(sm);
    const int tid = threadIdx.x;
    const int lane = tid & 31, wid = tid >> 5;
    const int wm = wid & 3, wn = wid >> 2;
    const int bm = blockIdx.y * 128, bn = blockIdx.x * 128;

    if ((bm & (NL - 1)) >= gLen[bm >> 10]) {
        if (EPI == 3) {
            const float4 z4 = make_float4(0.f, 0.f, 0.f, 0.f);
            #pragma unroll
            for (int it = 0; it < 16; it++) {
                int u = it * 256 + tid;
                int r = u >> 5, c = (u & 31) << 2;
                *(float4*)(Cf + (size_t)(bm + r) * N + bn + c) = z4;
            }
        }
        return;
    }

    float acc[2][8][4];
    #pragma unroll
    for (int i = 0; i < 2; i++)
        #pragma unroll
        for (int j = 0; j < 8; j++)
            #pragma unroll
            for (int c = 0; c < 4; c++) acc[i][j][c] = 0.f;

    const int nt = K >> 5;

    auto prefetch = [&](int stage, int kt) {
        const int k0 = kt << 5;
        #pragma unroll
        for (int it = 0; it < 8; it++) {
            int u = (it << 8) + tid;
            int mat = u >> 9, w = u & 511, r = w >> 2, c = w & 3;
            const __nv_bfloat16* g;
            int rb;
            if      (mat == 0) { g = Ahi; rb = bm; }
            else if (mat == 1) { g = Alo; rb = bm; }
            else if (mat == 2) { g = Bhi; rb = bn; }
            else               { g = Blo; rb = bn; }
            cpasync16(sb + (uint32_t)(stage * STAGE_B + mat * ATILE + r * 80 + (c << 4)),
                      g + (size_t)(rb + r) * K + k0 + (c << 3));
        }
        CP_COMMIT();
    };

    auto compute = [&](int stage) {
        const uint32_t stb = sb + (uint32_t)(stage * STAGE_B);
        const int g = lane >> 3;
        #pragma unroll
        for (int ks = 0; ks < 2; ks++) {
            uint32_t af[2][2][4];
            #pragma unroll
            for (int d = 0; d < 2; d++)
                #pragma unroll
                for (int fm = 0; fm < 2; fm++) {
                    int row = wm * 32 + fm * 16 + (lane & 15);
                    int chunk = ks * 2 + (lane >> 4);
                    uint32_t a = stb + (uint32_t)(d * ATILE + row * 80 + chunk * 16);
                    LDSM_X4(af[d][fm][0], af[d][fm][1], af[d][fm][2], af[d][fm][3], a);
                }
            uint32_t bf_[4][4];
            #pragma unroll
            for (int fq = 0; fq < 4; fq++) {
                int row = wn * 64 + fq * 16 + ((g >> 1) << 3) + (lane & 7);
                int chunk = ks * 2 + (g & 1);
                uint32_t a = stb + (uint32_t)(2 * ATILE + row * 80 + chunk * 16);
                LDSM_X4(bf_[fq][0], bf_[fq][1], bf_[fq][2], bf_[fq][3], a);
            }
            #pragma unroll
            for (int fm = 0; fm < 2; fm++)
                #pragma unroll
                for (int fn = 0; fn < 8; fn++) {
                    uint32_t b0 = bf_[fn >> 1][(fn & 1) * 2], b1 = bf_[fn >> 1][(fn & 1) * 2 + 1];
                    MMA16816(acc[fm][fn], af[0][fm], b0, b1);
                    MMA16816(acc[fm][fn], af[1][fm], b0, b1);
                }
            #pragma unroll
            for (int fq = 0; fq < 4; fq++) {
                int row = wn * 64 + fq * 16 + ((g >> 1) << 3) + (lane & 7);
                int chunk = ks * 2 + (g & 1);
                uint32_t a = stb + (uint32_t)(3 * ATILE + row * 80 + chunk * 16);
                LDSM_X4(bf_[fq][0], bf_[fq][1], bf_[fq][2], bf_[fq][3], a);
            }
            #pragma unroll
            for (int fm = 0; fm < 2; fm++)
                #pragma unroll
                for (int fn = 0; fn < 8; fn++) {
                    uint32_t b0 = bf_[fn >> 1][(fn & 1) * 2], b1 = bf_[fn >> 1][(fn & 1) * 2 + 1];
                    MMA16816(acc[fm][fn], af[0][fm], b0, b1);
                }
        }
    };

    prefetch(0, 0);
    for (int i = 0; i < nt; i++) {
        CP_WAIT(0);
        __syncthreads();
        if (i + 1 < nt) prefetch((i + 1) & 1, i + 1);
        compute(i & 1);
    }

    const int tq = lane >> 2, tr2 = (lane & 3) << 1;
    #pragma unroll
    for (int fm = 0; fm < 2; fm++) {
        #pragma unroll
        for (int fn = 0; fn < 8; fn++) {
            int col = bn + wn * 64 + fn * 8 + tr2;
            float b0 = __ldg(bias + col), b1 = __ldg(bias + col + 1);
            #pragma unroll
            for (int half = 0; half < 2; half++) {
                int row = bm + wm * 32 + fm * 16 + tq + half * 8;
                float v0 = acc[fm][fn][half * 2]     + b0;
                float v1 = acc[fm][fn][half * 2 + 1] + b1;
                if (EPI == 0) {
                    int t = col >> 8, h = (col & 255) >> 5, dh = col & 31;
                    int bb = row >> 10, ll = row & 1023;
                    size_t o = (((size_t)(bb * NH + h)) * NL + ll) * NDH + dh;
                    uint32_t hv = pack2_hi(v0, v1);
                    if (t == 0)      *(uint32_t*)(gQhi + o) = hv;
                    else if (t == 1) *(uint32_t*)(gKhi + o) = hv;
                    else             *(uint32_t*)(gVhi + o) = hv;
                } else if (EPI == 1) {
                    size_t o = (size_t)row * N + col;
                    v0 += __ldg(resf + o); v1 += __ldg(resf + o + 1);
                    *(uint32_t*)(Chi + o) = pack2_hi(v0, v1);
                    *(uint32_t*)(Clo + o) = pack2_lo(v0, v1);
                } else if (EPI == 2) {
                    size_t o = (size_t)row * N + col;
                    v0 = gelu_f(v0); v1 = gelu_f(v1);
                    *(uint32_t*)(Chi + o) = pack2_hi(v0, v1);
                    *(uint32_t*)(Clo + o) = pack2_lo(v0, v1);
                } else {
                    size_t o = (size_t)row * N + col;
                    uint32_t rh = *(const uint32_t*)(Chi + o);
                    uint32_t rl = *(const uint32_t*)(Clo + o);
                    v0 += __bfloat162float(__ushort_as_bfloat16((unsigned short)(rh & 0xffff)))
                        + __bfloat162float(__ushort_as_bfloat16((unsigned short)(rl & 0xffff)));
                    v1 += __bfloat162float(__ushort_as_bfloat16((unsigned short)(rh >> 16)))
                        + __bfloat162float(__ushort_as_bfloat16((unsigned short)(rl >> 16)));
                    int bb = row >> 10, ll = row & 1023;
                    if (ll >= gLen[bb]) { v0 = 0.f; v1 = 0.f; }
                    *(float2*)(Cf + o) = make_float2(v0, v1);
                }
            }
        }
    }
}

// ---------------- tensor-core flash attention (hi-only QK, R10 shape) ----------------
// 64 q rows/block, 64-key tiles, static smem 25.6KB, log2-domain softmax.
#define AQ_B 5120            // 64 rows x 80B
#define AKV_B (2*AQ_B)       // Khi + Vhi per stage

__global__ __launch_bounds__(128) void attn_mma_kernel() {
    __shared__ __align__(16) unsigned char smem[AQ_B + 2*AKV_B];
    const uint32_t sb = smem_u32(smem);
    const uint32_t sQhi = sb;
    const uint32_t sKV0 = sb + AQ_B;

    const int tid = threadIdx.x, lane = tid & 31, wq = tid >> 5;
    const int bh = blockIdx.y, b = bh >> 3, h = bh & 7;
    const int qbase = blockIdx.x * 64;
    const int g = lane >> 3;
    const int tq = lane >> 2, tt = lane & 3;

    const int S = gLen[b];
    if (qbase >= S) return;

    const __nv_bfloat16* Qh = gQhi + (size_t)bh * NL * NDH;
    const __nv_bfloat16* Kh = gKhi + (size_t)bh * NL * NDH;
    const __nv_bfloat16* Vh = gVhi + (size_t)bh * NL * NDH;

    const float LOG2E = 1.4426950408889634f;
    const float sf = (float)S;
    const float invs_l2 = LOG2E / sf;
    const float scale_l2 = 0.1767766952966369f * LOG2E;
    const int nt = (S + 63) >> 6;

    // stage Q hi (2 iterations x 128 threads = 256 16B-chunks)
    #pragma unroll
    for (int it = 0; it < 2; it++) {
        int u = (it << 7) + tid;
        int r = u >> 2, c = u & 3;
        cpasync16(sQhi + (uint32_t)(r * 80 + (c << 4)),
                  Qh + (size_t)(qbase + r) * NDH + (c << 3));
    }
    auto loadKV = [&](int stage, int kt) {
        uint32_t base = sKV0 + (uint32_t)stage * AKV_B;
        #pragma unroll
        for (int it = 0; it < 4; it++) {
            int u = (it << 7) + tid;           // 0..511
            int mat = u >> 8, w = u & 255, r = w >> 2, c = w & 3;
            const __nv_bfloat16* gp = (mat == 0) ? Kh : Vh;
            cpasync16(base + (uint32_t)(mat * AQ_B + r * 80 + (c << 4)),
                      gp + (size_t)(kt + r) * NDH + (c << 3));
        }
        CP_COMMIT();
    };
    loadKV(0, 0);

    uint32_t aQh[2][4];
    float oAcc[4][4];
    #pragma unroll
    for (int i = 0; i < 4; i++)
        #pragma unroll
        for (int j = 0; j < 4; j++) oAcc[i][j] = 0.f;
    float mrow0 = -1e30f, mrow1 = -1e30f, lp0 = 0.f, lp1 = 0.f;

    const float qr0 = (float)(qbase + wq * 16 + tq);
    const float qr1 = qr0 + 8.f;

    for (int i = 0; i < nt; i++) {
        if (i + 1 < nt) { loadKV((i + 1) & 1, (i + 1) << 6); CP_WAIT(1); }
        else            { CP_WAIT(0); }
        __syncthreads();

        if (i == 0) {
            #pragma unroll
            for (int ks = 0; ks < 2; ks++) {
                uint32_t roff = (uint32_t)((wq * 16 + ((g & 1) << 3) + (lane & 7)) * 80
                                           + 32 * ks + 16 * (g >> 1));
                LDSM_X4(aQh[ks][0], aQh[ks][1], aQh[ks][2], aQh[ks][3], sQhi + roff);
            }
        }

        const uint32_t sK = sKV0 + (uint32_t)(i & 1) * AKV_B;
        const uint32_t sV = sK + AQ_B;
        const int kt = i << 6;

        float sA[8][4];
        #pragma unroll
        for (int j = 0; j < 8; j++)
            #pragma unroll
            for (int c = 0; c < 4; c++) sA[j][c] = 0.f;

        #pragma unroll
        for (int ks = 0; ks < 2; ks++) {
            #pragma unroll
            for (int jp = 0; jp < 4; jp++) {
                uint32_t kh[4];
                uint32_t roff = (uint32_t)((16 * jp + ((g >> 1) << 3) + (lane & 7)) * 80
                                           + 32 * ks + 16 * (g & 1));
                LDSM_X4(kh[0], kh[1], kh[2], kh[3], sK + roff);
                MMA16816(sA[2*jp],     aQh[ks], kh[0], kh[1]);
                MMA16816(sA[2*jp + 1], aQh[ks], kh[2], kh[3]);
            }
        }

        // log2-domain bias + online softmax
        float x[8][4];
        float tmax0 = -1e30f, tmax1 = -1e30f;
        #pragma unroll
        for (int j = 0; j < 8; j++) {
            int kc = kt + 8 * j + 2 * tt;
            float k0f = (float)kc, k1f = k0f + 1.f;
            float b00 = (kc     < S) ? LOG2E - fabsf(qr0 - k0f) * invs_l2 : -1e30f;
            float b01 = (kc + 1 < S) ? LOG2E - fabsf(qr0 - k1f) * invs_l2 : -1e30f;
            float b10 = (kc     < S) ? LOG2E - fabsf(qr1 - k0f) * invs_l2 : -1e30f;
            float b11 = (kc + 1 < S) ? LOG2E - fabsf(qr1 - k1f) * invs_l2 : -1e30f;
            x[j][0] = fmaf(sA[j][0], scale_l2, b00);
            x[j][1] = fmaf(sA[j][1], scale_l2, b01);
            x[j][2] = fmaf(sA[j][2], scale_l2, b10);
            x[j][3] = fmaf(sA[j][3], scale_l2, b11);
            tmax0 = fmaxf(tmax0, fmaxf(x[j][0], x[j][1]));
            tmax1 = fmaxf(tmax1, fmaxf(x[j][2], x[j][3]));
        }
        tmax0 = fmaxf(tmax0, __shfl_xor_sync(0xffffffff, tmax0, 1));
        tmax0 = fmaxf(tmax0, __shfl_xor_sync(0xffffffff, tmax0, 2));
        tmax1 = fmaxf(tmax1, __shfl_xor_sync(0xffffffff, tmax1, 1));
        tmax1 = fmaxf(tmax1, __shfl_xor_sync(0xffffffff, tmax1, 2));
        float mn0 = fmaxf(mrow0, tmax0), mn1 = fmaxf(mrow1, tmax1);
        float corr0 = exp2f(mrow0 - mn0), corr1 = exp2f(mrow1 - mn1);
        mrow0 = mn0; mrow1 = mn1;
        lp0 *= corr0; lp1 *= corr1;
        #pragma unroll
        for (int nf = 0; nf < 4; nf++) {
            oAcc[nf][0] *= corr0; oAcc[nf][1] *= corr0;
            oAcc[nf][2] *= corr1; oAcc[nf][3] *= corr1;
        }

        uint32_t aP[4][4];
        #pragma unroll
        for (int j = 0; j < 8; j++) {
            float p0 = exp2f(x[j][0] - mn0), p1 = exp2f(x[j][1] - mn0);
            float p2 = exp2f(x[j][2] - mn1), p3 = exp2f(x[j][3] - mn1);
            lp0 += p0 + p1; lp1 += p2 + p3;
            int jp = j >> 1, s2 = (j & 1) << 1;
            aP[jp][s2]     = pack2_hi(p0, p1);
            aP[jp][s2 + 1] = pack2_hi(p2, p3);
        }

        #pragma unroll
        for (int jp = 0; jp < 4; jp++) {
            uint32_t bv[8];
            uint32_t roff = (uint32_t)((16 * jp + ((g & 1) << 3) + (lane & 7)) * 80
                                       + 16 * (g >> 1));
            LDSM_X4_T(bv[0], bv[1], bv[2], bv[3], sV + roff);
            LDSM_X4_T(bv[4], bv[5], bv[6], bv[7], sV + roff + 32);
            MMA16816(oAcc[0], aP[jp], bv[0], bv[1]);
            MMA16816(oAcc[1], aP[jp], bv[2], bv[3]);
            MMA16816(oAcc[2], aP[jp], bv[4], bv[5]);
            MMA16816(oAcc[3], aP[jp], bv[6], bv[7]);
        }
        __syncthreads();
    }

    lp0 += __shfl_xor_sync(0xffffffff, lp0, 1);
    lp0 += __shfl_xor_sync(0xffffffff, lp0, 2);
    lp1 += __shfl_xor_sync(0xffffffff, lp1, 1);
    lp1 += __shfl_xor_sync(0xffffffff, lp1, 2);
    float inv0 = 1.f / lp0, inv1 = 1.f / lp1;
    int r0 = qbase + wq * 16 + tq, r1 = r0 + 8;
    #pragma unroll
    for (int nf = 0; nf < 4; nf++) {
        int dh = 8 * nf + 2 * tt;
        size_t o0 = ((size_t)(b * NL + r0)) * ND + h * NDH + dh;
        size_t o1 = ((size_t)(b * NL + r1)) * ND + h * NDH + dh;
        float v00 = oAcc[nf][0] * inv0, v01 = oAcc[nf][1] * inv0;
        float v10 = oAcc[nf][2] * inv1, v11 = oAcc[nf][3] * inv1;
        *(uint32_t*)(gCtxHi + o0) = pack2_hi(v00, v01);
        *(uint32_t*)(gCtxLo + o0) = pack2_lo(v00, v01);
        *(uint32_t*)(gCtxHi + o1) = pack2_hi(v10, v11);
        *(uint32_t*)(gCtxLo + o1) = pack2_lo(v10, v11);
    }
}

// ---------------- launcher ----------------
extern "C" void kernel_launch(void* const* d_in, const int* in_sizes, int n_in,
                              void* d_out, int out_size) {
    const float* src       = (const float*)d_in[0];
    const unsigned char* mask = (const unsigned char*)d_in[1];
    const float* in_proj_w = (const float*)d_in[2];
    const float* in_proj_b = (const float*)d_in[3];
    const float* out_w     = (const float*)d_in[4];
    const float* out_b     = (const float*)d_in[5];
    const float* proj_w    = (const float*)d_in[6];
    const float* proj_b    = (const float*)d_in[7];
    const float* ff1_w     = (const float*)d_in[8];
    const float* ff1_b     = (const float*)d_in[9];
    const float* ff2_w     = (const float*)d_in[10];
    const float* ff2_b     = (const float*)d_in[11];
    float* out = (float*)d_out;

    cudaFuncSetAttribute(mma_gemm<0>, cudaFuncAttributeMaxDynamicSharedMemorySize, SMEM_DYN);
    cudaFuncSetAttribute(mma_gemm<1>, cudaFuncAttributeMaxDynamicSharedMemorySize, SMEM_DYN);
    cudaFuncSetAttribute(mma_gemm<2>, cudaFuncAttributeMaxDynamicSharedMemorySize, SMEM_DYN);
    cudaFuncSetAttribute(mma_gemm<3>, cudaFuncAttributeMaxDynamicSharedMemorySize, SMEM_DYN);

    float *pBc;
    __nv_bfloat16 *pSrcHi, *pSrcLo, *pCtxHi, *pCtxLo, *pHHi, *pHLo, *pFFHi, *pFFLo;
    __nv_bfloat16 *pWqkvHi, *pWqkvLo, *pWcHi, *pWcLo, *pW1Hi, *pW1Lo, *pW2Hi, *pW2Lo;
    cudaGetSymbolAddress((void**)&pBc, gBc);
    cudaGetSymbolAddress((void**)&pSrcHi, gSrcHi);  cudaGetSymbolAddress((void**)&pSrcLo, gSrcLo);
    cudaGetSymbolAddress((void**)&pCtxHi, gCtxHi);  cudaGetSymbolAddress((void**)&pCtxLo, gCtxLo);
    cudaGetSymbolAddress((void**)&pHHi, gHHi);      cudaGetSymbolAddress((void**)&pHLo, gHLo);
    cudaGetSymbolAddress((void**)&pFFHi, gFFHi);    cudaGetSymbolAddress((void**)&pFFLo, gFFLo);
    cudaGetSymbolAddress((void**)&pWqkvHi, gWqkvHi); cudaGetSymbolAddress((void**)&pWqkvLo, gWqkvLo);
    cudaGetSymbolAddress((void**)&pWcHi, gWcHi);    cudaGetSymbolAddress((void**)&pWcLo, gWcLo);
    cudaGetSymbolAddress((void**)&pW1Hi, gW1Hi);    cudaGetSymbolAddress((void**)&pW1Lo, gW1Lo);
    cudaGetSymbolAddress((void**)&pW2Hi, gW2Hi);    cudaGetSymbolAddress((void**)&pW2Lo, gW2Lo);

    setup_kernel<<<NB, 256>>>(mask);
    conv_all<<<(CN0+CN1+CN2+CN3 + 255)/256, 256>>>(src, in_proj_w, ff1_w, ff2_w);
    fuse_wb<<<ND + 1, ND>>>(proj_w, out_w, out_b, proj_b);

    // QKV = src @ in_proj_w^T + b -> bf16 Q/K/V (hi)
    mma_gemm<0><<<dim3(6, 64), 256, SMEM_DYN>>>(pSrcHi, pSrcLo, pWqkvHi, pWqkvLo,
        in_proj_b, nullptr, nullptr, nullptr, nullptr, NM, 3*ND, ND);
    // tensor-core attention (hi-only QK) -> ctx hi/lo
    attn_mma_kernel<<<dim3(16, 64), 128>>>();
    // H = src + ctx @ Wc^T + bc -> hi/lo only
    mma_gemm<1><<<dim3(2, 64), 256, SMEM_DYN>>>(pCtxHi, pCtxLo, pWcHi, pWcLo,
        pBc, nullptr, pHHi, pHLo, src, NM, ND, ND);
    // ff = gelu(H @ ff1_w^T + b1) -> hi/lo
    mma_gemm<2><<<dim3(16, 64), 256, SMEM_DYN>>>(pHHi, pHLo, pW1Hi, pW1Lo,
        ff1_b, nullptr, pFFHi, pFFLo, nullptr, NM, NDFF, ND);
    // out = (Hhi+Hlo) + ff @ ff2_w^T + b2, padded rows zeroed
    mma_gemm<3><<<dim3(2, 64), 256, SMEM_DYN>>>(pFFHi, pFFLo, pW2Hi, pW2Lo,
        ff2_b, out, pHHi, pHLo, nullptr, NM, ND, NDFF);
}

// round 13
// speedup vs baseline: 1.1110x; 1.0391x over previous
#include <cuda_runtime.h>
#include <cuda_bf16.h>
#include <math.h>
#include <stdint.h>

#define NB 8
#define NL 1024
#define ND 256
#define NH 8
#define NDH 32
#define NDFF 2048
#define NM (NB*NL)

// ---------------- scratch (device globals; allocation-free, zero-init) ----------------
__device__ __nv_bfloat16 gQhi[64*NL*NDH];
__device__ __nv_bfloat16 gKhi[64*NL*NDH];
__device__ __nv_bfloat16 gVhi[64*NL*NDH];
__device__ __nv_bfloat16 gSrcHi[NM*ND];
__device__ __nv_bfloat16 gCtxHi[NM*ND],  gCtxLo[NM*ND];
__device__ __nv_bfloat16 gHHi[NM*ND],    gHLo[NM*ND];
__device__ __nv_bfloat16 gFFHi[(size_t)NM*NDFF], gFFLo[(size_t)NM*NDFF];
__device__ __nv_bfloat16 gWqkvHi[3*ND*ND];
__device__ __nv_bfloat16 gWcHi[ND*ND],     gWcLo[ND*ND];
__device__ __nv_bfloat16 gW1Hi[NDFF*ND],   gW1Lo[NDFF*ND];
__device__ __nv_bfloat16 gW2Hi[ND*NDFF],   gW2Lo[ND*NDFF];
__device__ float gBc[ND];
__device__ int   gLen[NB];

// ---------------- helpers ----------------
__device__ __forceinline__ uint32_t smem_u32(const void* p) {
    uint32_t a;
    asm("{ .reg .u64 t; cvta.to.shared.u64 t, %1; cvt.u32.u64 %0, t; }" : "=r"(a) : "l"(p));
    return a;
}
__device__ __forceinline__ void cpasync16(uint32_t saddr, const void* gaddr) {
    asm volatile("cp.async.cg.shared.global [%0], [%1], 16;" :: "r"(saddr), "l"(gaddr) : "memory");
}
#define CP_COMMIT() asm volatile("cp.async.commit_group;" ::: "memory")
#define CP_WAIT(n)  asm volatile("cp.async.wait_group %0;" :: "n"(n) : "memory")

#define LDSM_X4(r0, r1, r2, r3, addr) \
    asm volatile("ldmatrix.sync.aligned.m8n8.x4.shared.b16 {%0,%1,%2,%3}, [%4];" \
        : "=r"(r0), "=r"(r1), "=r"(r2), "=r"(r3) : "r"(addr))
#define LDSM_X4_T(r0, r1, r2, r3, addr) \
    asm volatile("ldmatrix.sync.aligned.m8n8.x4.trans.shared.b16 {%0,%1,%2,%3}, [%4];" \
        : "=r"(r0), "=r"(r1), "=r"(r2), "=r"(r3) : "r"(addr))

#define MMA16816(d, a, b0, b1) \
    asm volatile("mma.sync.aligned.m16n8k16.row.col.f32.bf16.bf16.f32 " \
        "{%0,%1,%2,%3}, {%4,%5,%6,%7}, {%8,%9}, {%0,%1,%2,%3};" \
        : "+f"((d)[0]), "+f"((d)[1]), "+f"((d)[2]), "+f"((d)[3]) \
        : "r"((a)[0]), "r"((a)[1]), "r"((a)[2]), "r"((a)[3]), "r"(b0), "r"(b1))

__device__ __forceinline__ float gelu_f(float x) {
    return 0.5f * x * (1.f + erff(x * 0.7071067811865475f));
}
__device__ __forceinline__ uint32_t pack2_hi(float a, float b) {
    __nv_bfloat16 h0 = __float2bfloat16(a), h1 = __float2bfloat16(b);
    return ((uint32_t)__bfloat16_as_ushort(h1) << 16) | __bfloat16_as_ushort(h0);
}
__device__ __forceinline__ uint32_t pack2_lo(float a, float b) {
    __nv_bfloat16 h0 = __float2bfloat16(a), h1 = __float2bfloat16(b);
    float l0 = a - __bfloat162float(h0), l1 = b - __bfloat162float(h1);
    __nv_bfloat16 g0 = __float2bfloat16(l0), g1 = __float2bfloat16(l1);
    return ((uint32_t)__bfloat16_as_ushort(g1) << 16) | __bfloat16_as_ushort(g0);
}

// ---------------- setup: 8 blocks ----------------
__global__ __launch_bounds__(256) void setup_kernel(const unsigned char* __restrict__ mb) {
    __shared__ int flag, cnt;
    const int b = blockIdx.x, tid = threadIdx.x;
    if (tid == 0) { flag = 0; cnt = 0; }
    __syncthreads();
    int f = 0;
    for (int i = tid; i < NB*NL; i += 256)
        if ((i & 3) != 0 && mb[i] != 0) f = 1;
    if (f) atomicOr(&flag, 1);
    __syncthreads();
    const int mode = flag;
    int c = 0;
    for (int i = tid; i < NL; i += 256) {
        int pad = mode ? (mb[b*NL + i] != 0) : (((const int*)mb)[b*NL + i] != 0);
        if (!pad) c++;
    }
    atomicAdd(&cnt, c);
    __syncthreads();
    if (tid == 0) gLen[b] = cnt;
}

// ---------------- merged fp32 -> bf16 conversion ----------------
// src + in_proj_w: hi only (feed hi-only QKV GEMM). ff1_w/ff2_w: hi+lo.
#define CN0 (NM*ND/4)
#define CN1 (3*ND*ND/4)
#define CN2 (NDFF*ND/4)
#define CN3 (ND*NDFF/4)
__global__ void conv_all(const float* __restrict__ src, const float* __restrict__ w0,
                         const float* __restrict__ w1, const float* __restrict__ w2) {
    int i = blockIdx.x * 256 + threadIdx.x;
    const float* x; __nv_bfloat16 *hi, *lo;
    if (i < CN0)                 { x = src; hi = gSrcHi;  lo = nullptr; }
    else if (i < CN0+CN1)        { i -= CN0; x = w0; hi = gWqkvHi; lo = nullptr; }
    else if (i < CN0+CN1+CN2)    { i -= CN0+CN1; x = w1; hi = gW1Hi; lo = gW1Lo; }
    else if (i < CN0+CN1+CN2+CN3){ i -= CN0+CN1+CN2; x = w2; hi = gW2Hi; lo = gW2Lo; }
    else return;
    float4 f = ((const float4*)x)[i];
    uint2 h;
    h.x = pack2_hi(f.x, f.y); h.y = pack2_hi(f.z, f.w);
    ((uint2*)hi)[i] = h;
    if (lo) {
        uint2 l;
        l.x = pack2_lo(f.x, f.y); l.y = pack2_lo(f.z, f.w);
        ((uint2*)lo)[i] = l;
    }
}

// ---------------- merged weight+bias fusion ----------------
__global__ void fuse_wb(const float* __restrict__ pw, const float* __restrict__ ow,
                        const float* __restrict__ ob, const float* __restrict__ pb) {
    int i = blockIdx.x, j = threadIdx.x;
    if (i == ND) {
        float s = pb[j];
        #pragma unroll 8
        for (int k = 0; k < ND; k++)
            s = fmaf(pw[j*ND + k], ob[k], s);
        gBc[j] = s;
        return;
    }
    float s = 0.f;
    #pragma unroll 8
    for (int k = 0; k < ND; k++)
        s = fmaf(pw[i*ND + k], ow[k*ND + j], s);
    __nv_bfloat16 h = __float2bfloat16(s);
    gWcHi[i*ND + j] = h;
    gWcLo[i*ND + j] = __float2bfloat16(s - __bfloat162float(h));
}

// ---------------- mma.sync GEMM: FULL = split-bf16 3-product, !FULL = hi-only ------
// 128x128 tile, 8 warps 4m x 2n, 2-stage K=32 pipeline, single sync/iter.
// EPI 0: QKV scatter (+bias) -> bf16 Q/K/V hi  (used with FULL=false)
// EPI 1: H = res + acc + bias -> hi/lo only
// EPI 2: gelu(acc+bias) -> hi/lo only
// EPI 3: out = (Chi+Clo) + acc + bias, padded rows zeroed, fp32
#define ATILE (128*80)
#define SMEM_FULL (2*4*ATILE)     // 81920
#define SMEM_HI   (2*2*ATILE)     // 40960

template<int EPI, bool FULL>
__global__ __launch_bounds__(256, 2) void mma_gemm(
    const __nv_bfloat16* __restrict__ Ahi, const __nv_bfloat16* __restrict__ Alo,
    const __nv_bfloat16* __restrict__ Bhi, const __nv_bfloat16* __restrict__ Blo,
    const float* __restrict__ bias,
    float* __restrict__ Cf, __nv_bfloat16* __restrict__ Chi, __nv_bfloat16* __restrict__ Clo,
    const float* __restrict__ resf, int M, int N, int K)
{
    constexpr int NMAT = FULL ? 4 : 2;
    constexpr int STAGE = NMAT * ATILE;

    extern __shared__ char sm[];
    const uint32_t sb = smem_u32(sm);
    const int tid = threadIdx.x;
    const int lane = tid & 31, wid = tid >> 5;
    const int wm = wid & 3, wn = wid >> 2;
    const int bm = blockIdx.y * 128, bn = blockIdx.x * 128;

    if ((bm & (NL - 1)) >= gLen[bm >> 10]) {
        if (EPI == 3) {
            const float4 z4 = make_float4(0.f, 0.f, 0.f, 0.f);
            #pragma unroll
            for (int it = 0; it < 16; it++) {
                int u = it * 256 + tid;
                int r = u >> 5, c = (u & 31) << 2;
                *(float4*)(Cf + (size_t)(bm + r) * N + bn + c) = z4;
            }
        }
        return;
    }

    float acc[2][8][4];
    #pragma unroll
    for (int i = 0; i < 2; i++)
        #pragma unroll
        for (int j = 0; j < 8; j++)
            #pragma unroll
            for (int c = 0; c < 4; c++) acc[i][j][c] = 0.f;

    const int nt = K >> 5;

    auto prefetch = [&](int stage, int kt) {
        const int k0 = kt << 5;
        #pragma unroll
        for (int it = 0; it < NMAT * 2; it++) {
            int u = (it << 8) + tid;
            int mat = u >> 9, w = u & 511, r = w >> 2, c = w & 3;
            const __nv_bfloat16* g;
            int rb;
            if (FULL) {
                if      (mat == 0) { g = Ahi; rb = bm; }
                else if (mat == 1) { g = Alo; rb = bm; }
                else if (mat == 2) { g = Bhi; rb = bn; }
                else               { g = Blo; rb = bn; }
            } else {
                if (mat == 0) { g = Ahi; rb = bm; }
                else          { g = Bhi; rb = bn; }
            }
            cpasync16(sb + (uint32_t)(stage * STAGE + mat * ATILE + r * 80 + (c << 4)),
                      g + (size_t)(rb + r) * K + k0 + (c << 3));
        }
        CP_COMMIT();
    };

    auto compute = [&](int stage) {
        const uint32_t stb = sb + (uint32_t)(stage * STAGE);
        const int g = lane >> 3;
        #pragma unroll
        for (int ks = 0; ks < 2; ks++) {
            if (FULL) {
                uint32_t af[2][2][4];
                #pragma unroll
                for (int d = 0; d < 2; d++)
                    #pragma unroll
                    for (int fm = 0; fm < 2; fm++) {
                        int row = wm * 32 + fm * 16 + (lane & 15);
                        int chunk = ks * 2 + (lane >> 4);
                        uint32_t a = stb + (uint32_t)(d * ATILE + row * 80 + chunk * 16);
                        LDSM_X4(af[d][fm][0], af[d][fm][1], af[d][fm][2], af[d][fm][3], a);
                    }
                uint32_t bf_[4][4];
                #pragma unroll
                for (int fq = 0; fq < 4; fq++) {
                    int row = wn * 64 + fq * 16 + ((g >> 1) << 3) + (lane & 7);
                    int chunk = ks * 2 + (g & 1);
                    uint32_t a = stb + (uint32_t)(2 * ATILE + row * 80 + chunk * 16);
                    LDSM_X4(bf_[fq][0], bf_[fq][1], bf_[fq][2], bf_[fq][3], a);
                }
                #pragma unroll
                for (int fm = 0; fm < 2; fm++)
                    #pragma unroll
                    for (int fn = 0; fn < 8; fn++) {
                        uint32_t b0 = bf_[fn >> 1][(fn & 1) * 2], b1 = bf_[fn >> 1][(fn & 1) * 2 + 1];
                        MMA16816(acc[fm][fn], af[0][fm], b0, b1);
                        MMA16816(acc[fm][fn], af[1][fm], b0, b1);
                    }
                #pragma unroll
                for (int fq = 0; fq < 4; fq++) {
                    int row = wn * 64 + fq * 16 + ((g >> 1) << 3) + (lane & 7);
                    int chunk = ks * 2 + (g & 1);
                    uint32_t a = stb + (uint32_t)(3 * ATILE + row * 80 + chunk * 16);
                    LDSM_X4(bf_[fq][0], bf_[fq][1], bf_[fq][2], bf_[fq][3], a);
                }
                #pragma unroll
                for (int fm = 0; fm < 2; fm++)
                    #pragma unroll
                    for (int fn = 0; fn < 8; fn++) {
                        uint32_t b0 = bf_[fn >> 1][(fn & 1) * 2], b1 = bf_[fn >> 1][(fn & 1) * 2 + 1];
                        MMA16816(acc[fm][fn], af[0][fm], b0, b1);
                    }
            } else {
                uint32_t af[2][4];
                #pragma unroll
                for (int fm = 0; fm < 2; fm++) {
                    int row = wm * 32 + fm * 16 + (lane & 15);
                    int chunk = ks * 2 + (lane >> 4);
                    uint32_t a = stb + (uint32_t)(row * 80 + chunk * 16);
                    LDSM_X4(af[fm][0], af[fm][1], af[fm][2], af[fm][3], a);
                }
                uint32_t bf_[4][4];
                #pragma unroll
                for (int fq = 0; fq < 4; fq++) {
                    int row = wn * 64 + fq * 16 + ((g >> 1) << 3) + (lane & 7);
                    int chunk = ks * 2 + (g & 1);
                    uint32_t a = stb + (uint32_t)(ATILE + row * 80 + chunk * 16);
                    LDSM_X4(bf_[fq][0], bf_[fq][1], bf_[fq][2], bf_[fq][3], a);
                }
                #pragma unroll
                for (int fm = 0; fm < 2; fm++)
                    #pragma unroll
                    for (int fn = 0; fn < 8; fn++) {
                        uint32_t b0 = bf_[fn >> 1][(fn & 1) * 2], b1 = bf_[fn >> 1][(fn & 1) * 2 + 1];
                        MMA16816(acc[fm][fn], af[fm], b0, b1);
                    }
            }
        }
    };

    prefetch(0, 0);
    for (int i = 0; i < nt; i++) {
        CP_WAIT(0);
        __syncthreads();
        if (i + 1 < nt) prefetch((i + 1) & 1, i + 1);
        compute(i & 1);
    }

    const int tq = lane >> 2, tr2 = (lane & 3) << 1;
    #pragma unroll
    for (int fm = 0; fm < 2; fm++) {
        #pragma unroll
        for (int fn = 0; fn < 8; fn++) {
            int col = bn + wn * 64 + fn * 8 + tr2;
            float b0 = __ldg(bias + col), b1 = __ldg(bias + col + 1);
            #pragma unroll
            for (int half = 0; half < 2; half++) {
                int row = bm + wm * 32 + fm * 16 + tq + half * 8;
                float v0 = acc[fm][fn][half * 2]     + b0;
                float v1 = acc[fm][fn][half * 2 + 1] + b1;
                if (EPI == 0) {
                    int t = col >> 8, h = (col & 255) >> 5, dh = col & 31;
                    int bb = row >> 10, ll = row & 1023;
                    size_t o = (((size_t)(bb * NH + h)) * NL + ll) * NDH + dh;
                    uint32_t hv = pack2_hi(v0, v1);
                    if (t == 0)      *(uint32_t*)(gQhi + o) = hv;
                    else if (t == 1) *(uint32_t*)(gKhi + o) = hv;
                    else             *(uint32_t*)(gVhi + o) = hv;
                } else if (EPI == 1) {
                    size_t o = (size_t)row * N + col;
                    v0 += __ldg(resf + o); v1 += __ldg(resf + o + 1);
                    *(uint32_t*)(Chi + o) = pack2_hi(v0, v1);
                    *(uint32_t*)(Clo + o) = pack2_lo(v0, v1);
                } else if (EPI == 2) {
                    size_t o = (size_t)row * N + col;
                    v0 = gelu_f(v0); v1 = gelu_f(v1);
                    *(uint32_t*)(Chi + o) = pack2_hi(v0, v1);
                    *(uint32_t*)(Clo + o) = pack2_lo(v0, v1);
                } else {
                    size_t o = (size_t)row * N + col;
                    uint32_t rh = *(const uint32_t*)(Chi + o);
                    uint32_t rl = *(const uint32_t*)(Clo + o);
                    v0 += __bfloat162float(__ushort_as_bfloat16((unsigned short)(rh & 0xffff)))
                        + __bfloat162float(__ushort_as_bfloat16((unsigned short)(rl & 0xffff)));
                    v1 += __bfloat162float(__ushort_as_bfloat16((unsigned short)(rh >> 16)))
                        + __bfloat162float(__ushort_as_bfloat16((unsigned short)(rl >> 16)));
                    int bb = row >> 10, ll = row & 1023;
                    if (ll >= gLen[bb]) { v0 = 0.f; v1 = 0.f; }
                    *(float2*)(Cf + o) = make_float2(v0, v1);
                }
            }
        }
    }
}

// ---------------- tensor-core flash attention (hi-only QK, R12 winner) --------------
#define AQ_B 5120            // 64 rows x 80B
#define AKV_B (2*AQ_B)       // Khi + Vhi per stage

__global__ __launch_bounds__(128) void attn_mma_kernel() {
    __shared__ __align__(16) unsigned char smem[AQ_B + 2*AKV_B];
    const uint32_t sb = smem_u32(smem);
    const uint32_t sQhi = sb;
    const uint32_t sKV0 = sb + AQ_B;

    const int tid = threadIdx.x, lane = tid & 31, wq = tid >> 5;
    const int bh = blockIdx.y, b = bh >> 3, h = bh & 7;
    const int qbase = blockIdx.x * 64;
    const int g = lane >> 3;
    const int tq = lane >> 2, tt = lane & 3;

    const int S = gLen[b];
    if (qbase >= S) return;

    const __nv_bfloat16* Qh = gQhi + (size_t)bh * NL * NDH;
    const __nv_bfloat16* Kh = gKhi + (size_t)bh * NL * NDH;
    const __nv_bfloat16* Vh = gVhi + (size_t)bh * NL * NDH;

    const float LOG2E = 1.4426950408889634f;
    const float sf = (float)S;
    const float invs_l2 = LOG2E / sf;
    const float scale_l2 = 0.1767766952966369f * LOG2E;
    const int nt = (S + 63) >> 6;

    #pragma unroll
    for (int it = 0; it < 2; it++) {
        int u = (it << 7) + tid;
        int r = u >> 2, c = u & 3;
        cpasync16(sQhi + (uint32_t)(r * 80 + (c << 4)),
                  Qh + (size_t)(qbase + r) * NDH + (c << 3));
    }
    auto loadKV = [&](int stage, int kt) {
        uint32_t base = sKV0 + (uint32_t)stage * AKV_B;
        #pragma unroll
        for (int it = 0; it < 4; it++) {
            int u = (it << 7) + tid;
            int mat = u >> 8, w = u & 255, r = w >> 2, c = w & 3;
            const __nv_bfloat16* gp = (mat == 0) ? Kh : Vh;
            cpasync16(base + (uint32_t)(mat * AQ_B + r * 80 + (c << 4)),
                      gp + (size_t)(kt + r) * NDH + (c << 3));
        }
        CP_COMMIT();
    };
    loadKV(0, 0);

    uint32_t aQh[2][4];
    float oAcc[4][4];
    #pragma unroll
    for (int i = 0; i < 4; i++)
        #pragma unroll
        for (int j = 0; j < 4; j++) oAcc[i][j] = 0.f;
    float mrow0 = -1e30f, mrow1 = -1e30f, lp0 = 0.f, lp1 = 0.f;

    const float qr0 = (float)(qbase + wq * 16 + tq);
    const float qr1 = qr0 + 8.f;

    for (int i = 0; i < nt; i++) {
        if (i + 1 < nt) { loadKV((i + 1) & 1, (i + 1) << 6); CP_WAIT(1); }
        else            { CP_WAIT(0); }
        __syncthreads();

        if (i == 0) {
            #pragma unroll
            for (int ks = 0; ks < 2; ks++) {
                uint32_t roff = (uint32_t)((wq * 16 + ((g & 1) << 3) + (lane & 7)) * 80
                                           + 32 * ks + 16 * (g >> 1));
                LDSM_X4(aQh[ks][0], aQh[ks][1], aQh[ks][2], aQh[ks][3], sQhi + roff);
            }
        }

        const uint32_t sK = sKV0 + (uint32_t)(i & 1) * AKV_B;
        const uint32_t sV = sK + AQ_B;
        const int kt = i << 6;

        float sA[8][4];
        #pragma unroll
        for (int j = 0; j < 8; j++)
            #pragma unroll
            for (int c = 0; c < 4; c++) sA[j][c] = 0.f;

        #pragma unroll
        for (int ks = 0; ks < 2; ks++) {
            #pragma unroll
            for (int jp = 0; jp < 4; jp++) {
                uint32_t kh[4];
                uint32_t roff = (uint32_t)((16 * jp + ((g >> 1) << 3) + (lane & 7)) * 80
                                           + 32 * ks + 16 * (g & 1));
                LDSM_X4(kh[0], kh[1], kh[2], kh[3], sK + roff);
                MMA16816(sA[2*jp],     aQh[ks], kh[0], kh[1]);
                MMA16816(sA[2*jp + 1], aQh[ks], kh[2], kh[3]);
            }
        }

        float x[8][4];
        float tmax0 = -1e30f, tmax1 = -1e30f;
        #pragma unroll
        for (int j = 0; j < 8; j++) {
            int kc = kt + 8 * j + 2 * tt;
            float k0f = (float)kc, k1f = k0f + 1.f;
            float b00 = (kc     < S) ? LOG2E - fabsf(qr0 - k0f) * invs_l2 : -1e30f;
            float b01 = (kc + 1 < S) ? LOG2E - fabsf(qr0 - k1f) * invs_l2 : -1e30f;
            float b10 = (kc     < S) ? LOG2E - fabsf(qr1 - k0f) * invs_l2 : -1e30f;
            float b11 = (kc + 1 < S) ? LOG2E - fabsf(qr1 - k1f) * invs_l2 : -1e30f;
            x[j][0] = fmaf(sA[j][0], scale_l2, b00);
            x[j][1] = fmaf(sA[j][1], scale_l2, b01);
            x[j][2] = fmaf(sA[j][2], scale_l2, b10);
            x[j][3] = fmaf(sA[j][3], scale_l2, b11);
            tmax0 = fmaxf(tmax0, fmaxf(x[j][0], x[j][1]));
            tmax1 = fmaxf(tmax1, fmaxf(x[j][2], x[j][3]));
        }
        tmax0 = fmaxf(tmax0, __shfl_xor_sync(0xffffffff, tmax0, 1));
        tmax0 = fmaxf(tmax0, __shfl_xor_sync(0xffffffff, tmax0, 2));
        tmax1 = fmaxf(tmax1, __shfl_xor_sync(0xffffffff, tmax1, 1));
        tmax1 = fmaxf(tmax1, __shfl_xor_sync(0xffffffff, tmax1, 2));
        float mn0 = fmaxf(mrow0, tmax0), mn1 = fmaxf(mrow1, tmax1);
        float corr0 = exp2f(mrow0 - mn0), corr1 = exp2f(mrow1 - mn1);
        mrow0 = mn0; mrow1 = mn1;
        lp0 *= corr0; lp1 *= corr1;
        #pragma unroll
        for (int nf = 0; nf < 4; nf++) {
            oAcc[nf][0] *= corr0; oAcc[nf][1] *= corr0;
            oAcc[nf][2] *= corr1; oAcc[nf][3] *= corr1;
        }

        uint32_t aP[4][4];
        #pragma unroll
        for (int j = 0; j < 8; j++) {
            float p0 = exp2f(x[j][0] - mn0), p1 = exp2f(x[j][1] - mn0);
            float p2 = exp2f(x[j][2] - mn1), p3 = exp2f(x[j][3] - mn1);
            lp0 += p0 + p1; lp1 += p2 + p3;
            int jp = j >> 1, s2 = (j & 1) << 1;
            aP[jp][s2]     = pack2_hi(p0, p1);
            aP[jp][s2 + 1] = pack2_hi(p2, p3);
        }

        #pragma unroll
        for (int jp = 0; jp < 4; jp++) {
            uint32_t bv[8];
            uint32_t roff = (uint32_t)((16 * jp + ((g & 1) << 3) + (lane & 7)) * 80
                                       + 16 * (g >> 1));
            LDSM_X4_T(bv[0], bv[1], bv[2], bv[3], sV + roff);
            LDSM_X4_T(bv[4], bv[5], bv[6], bv[7], sV + roff + 32);
            MMA16816(oAcc[0], aP[jp], bv[0], bv[1]);
            MMA16816(oAcc[1], aP[jp], bv[2], bv[3]);
            MMA16816(oAcc[2], aP[jp], bv[4], bv[5]);
            MMA16816(oAcc[3], aP[jp], bv[6], bv[7]);
        }
        __syncthreads();
    }

    lp0 += __shfl_xor_sync(0xffffffff, lp0, 1);
    lp0 += __shfl_xor_sync(0xffffffff, lp0, 2);
    lp1 += __shfl_xor_sync(0xffffffff, lp1, 1);
    lp1 += __shfl_xor_sync(0xffffffff, lp1, 2);
    float inv0 = 1.f / lp0, inv1 = 1.f / lp1;
    int r0 = qbase + wq * 16 + tq, r1 = r0 + 8;
    #pragma unroll
    for (int nf = 0; nf < 4; nf++) {
        int dh = 8 * nf + 2 * tt;
        size_t o0 = ((size_t)(b * NL + r0)) * ND + h * NDH + dh;
        size_t o1 = ((size_t)(b * NL + r1)) * ND + h * NDH + dh;
        float v00 = oAcc[nf][0] * inv0, v01 = oAcc[nf][1] * inv0;
        float v10 = oAcc[nf][2] * inv1, v11 = oAcc[nf][3] * inv1;
        *(uint32_t*)(gCtxHi + o0) = pack2_hi(v00, v01);
        *(uint32_t*)(gCtxLo + o0) = pack2_lo(v00, v01);
        *(uint32_t*)(gCtxHi + o1) = pack2_hi(v10, v11);
        *(uint32_t*)(gCtxLo + o1) = pack2_lo(v10, v11);
    }
}

// ---------------- launcher ----------------
extern "C" void kernel_launch(void* const* d_in, const int* in_sizes, int n_in,
                              void* d_out, int out_size) {
    const float* src       = (const float*)d_in[0];
    const unsigned char* mask = (const unsigned char*)d_in[1];
    const float* in_proj_w = (const float*)d_in[2];
    const float* in_proj_b = (const float*)d_in[3];
    const float* out_w     = (const float*)d_in[4];
    const float* out_b     = (const float*)d_in[5];
    const float* proj_w    = (const float*)d_in[6];
    const float* proj_b    = (const float*)d_in[7];
    const float* ff1_w     = (const float*)d_in[8];
    const float* ff1_b     = (const float*)d_in[9];
    const float* ff2_w     = (const float*)d_in[10];
    const float* ff2_b     = (const float*)d_in[11];
    float* out = (float*)d_out;

    cudaFuncSetAttribute((void*)mma_gemm<0,false>, cudaFuncAttributeMaxDynamicSharedMemorySize, SMEM_HI);
    cudaFuncSetAttribute((void*)mma_gemm<1,true>,  cudaFuncAttributeMaxDynamicSharedMemorySize, SMEM_FULL);
    cudaFuncSetAttribute((void*)mma_gemm<2,true>,  cudaFuncAttributeMaxDynamicSharedMemorySize, SMEM_FULL);
    cudaFuncSetAttribute((void*)mma_gemm<3,true>,  cudaFuncAttributeMaxDynamicSharedMemorySize, SMEM_FULL);

    float *pBc;
    __nv_bfloat16 *pSrcHi, *pCtxHi, *pCtxLo, *pHHi, *pHLo, *pFFHi, *pFFLo;
    __nv_bfloat16 *pWqkvHi, *pWcHi, *pWcLo, *pW1Hi, *pW1Lo, *pW2Hi, *pW2Lo;
    cudaGetSymbolAddress((void**)&pBc, gBc);
    cudaGetSymbolAddress((void**)&pSrcHi, gSrcHi);
    cudaGetSymbolAddress((void**)&pCtxHi, gCtxHi);  cudaGetSymbolAddress((void**)&pCtxLo, gCtxLo);
    cudaGetSymbolAddress((void**)&pHHi, gHHi);      cudaGetSymbolAddress((void**)&pHLo, gHLo);
    cudaGetSymbolAddress((void**)&pFFHi, gFFHi);    cudaGetSymbolAddress((void**)&pFFLo, gFFLo);
    cudaGetSymbolAddress((void**)&pWqkvHi, gWqkvHi);
    cudaGetSymbolAddress((void**)&pWcHi, gWcHi);    cudaGetSymbolAddress((void**)&pWcLo, gWcLo);
    cudaGetSymbolAddress((void**)&pW1Hi, gW1Hi);    cudaGetSymbolAddress((void**)&pW1Lo, gW1Lo);
    cudaGetSymbolAddress((void**)&pW2Hi, gW2Hi);    cudaGetSymbolAddress((void**)&pW2Lo, gW2Lo);

    setup_kernel<<<NB, 256>>>(mask);
    conv_all<<<(CN0+CN1+CN2+CN3 + 255)/256, 256>>>(src, in_proj_w, ff1_w, ff2_w);
    fuse_wb<<<ND + 1, ND>>>(proj_w, out_w, out_b, proj_b);

    // QKV = src @ in_proj_w^T + b (hi-only) -> bf16 Q/K/V
    mma_gemm<0,false><<<dim3(6, 64), 256, SMEM_HI>>>(pSrcHi, nullptr, pWqkvHi, nullptr,
        in_proj_b, nullptr, nullptr, nullptr, nullptr, NM, 3*ND, ND);
    // tensor-core attention (hi-only QK) -> ctx hi/lo
    attn_mma_kernel<<<dim3(16, 64), 128>>>();
    // H = src + ctx @ Wc^T + bc -> hi/lo only
    mma_gemm<1,true><<<dim3(2, 64), 256, SMEM_FULL>>>(pCtxHi, pCtxLo, pWcHi, pWcLo,
        pBc, nullptr, pHHi, pHLo, src, NM, ND, ND);
    // ff = gelu(H @ ff1_w^T + b1) -> hi/lo
    mma_gemm<2,true><<<dim3(16, 64), 256, SMEM_FULL>>>(pHHi, pHLo, pW1Hi, pW1Lo,
        ff1_b, nullptr, pFFHi, pFFLo, nullptr, NM, NDFF, ND);
    // out = (Hhi+Hlo) + ff @ ff2_w^T + b2, padded rows zeroed
    mma_gemm<3,true><<<dim3(2, 64), 256, SMEM_FULL>>>(pFFHi, pFFLo, pW2Hi, pW2Lo,
        ff2_b, out, pHHi, pHLo, nullptr, NM, ND, NDFF);
}

// round 14
// speedup vs baseline: 1.3605x; 1.2246x over previous
#include <cuda_runtime.h>
#include <cuda_bf16.h>
#include <math.h>
#include <stdint.h>

#define NB 8
#define NL 1024
#define ND 256
#define NH 8
#define NDH 32
#define NDFF 2048
#define NM (NB*NL)

// ---------------- scratch (device globals; allocation-free, zero-init) ----------------
__device__ __nv_bfloat16 gQhi[64*NL*NDH];
__device__ __nv_bfloat16 gKhi[64*NL*NDH];
__device__ __nv_bfloat16 gVhi[64*NL*NDH];
__device__ __nv_bfloat16 gSrcHi[NM*ND];
__device__ __nv_bfloat16 gCtxHi[NM*ND];
__device__ __nv_bfloat16 gHHi[NM*ND], gHLo[NM*ND];
__device__ __nv_bfloat16 gFFHi[(size_t)NM*NDFF];
__device__ __nv_bfloat16 gWqkvHi[3*ND*ND];
__device__ __nv_bfloat16 gWcHi[ND*ND],   gWcLo[ND*ND];
__device__ __nv_bfloat16 gW1Hi[NDFF*ND], gW1Lo[NDFF*ND];
__device__ __nv_bfloat16 gW2Hi[ND*NDFF], gW2Lo[ND*NDFF];
__device__ float gBc[ND];
__device__ int   gLen[NB];

// ---------------- helpers ----------------
__device__ __forceinline__ uint32_t smem_u32(const void* p) {
    uint32_t a;
    asm("{ .reg .u64 t; cvta.to.shared.u64 t, %1; cvt.u32.u64 %0, t; }" : "=r"(a) : "l"(p));
    return a;
}
__device__ __forceinline__ void cpasync16(uint32_t saddr, const void* gaddr) {
    asm volatile("cp.async.cg.shared.global [%0], [%1], 16;" :: "r"(saddr), "l"(gaddr) : "memory");
}
#define CP_COMMIT() asm volatile("cp.async.commit_group;" ::: "memory")
#define CP_WAIT(n)  asm volatile("cp.async.wait_group %0;" :: "n"(n) : "memory")

#define LDSM_X4(r0, r1, r2, r3, addr) \
    asm volatile("ldmatrix.sync.aligned.m8n8.x4.shared.b16 {%0,%1,%2,%3}, [%4];" \
        : "=r"(r0), "=r"(r1), "=r"(r2), "=r"(r3) : "r"(addr))
#define LDSM_X4_T(r0, r1, r2, r3, addr) \
    asm volatile("ldmatrix.sync.aligned.m8n8.x4.trans.shared.b16 {%0,%1,%2,%3}, [%4];" \
        : "=r"(r0), "=r"(r1), "=r"(r2), "=r"(r3) : "r"(addr))

#define MMA16816(d, a, b0, b1) \
    asm volatile("mma.sync.aligned.m16n8k16.row.col.f32.bf16.bf16.f32 " \
        "{%0,%1,%2,%3}, {%4,%5,%6,%7}, {%8,%9}, {%0,%1,%2,%3};" \
        : "+f"((d)[0]), "+f"((d)[1]), "+f"((d)[2]), "+f"((d)[3]) \
        : "r"((a)[0]), "r"((a)[1]), "r"((a)[2]), "r"((a)[3]), "r"(b0), "r"(b1))

__device__ __forceinline__ float gelu_f(float x) {
    return 0.5f * x * (1.f + erff(x * 0.7071067811865475f));
}
__device__ __forceinline__ uint32_t pack2_hi(float a, float b) {
    __nv_bfloat16 h0 = __float2bfloat16(a), h1 = __float2bfloat16(b);
    return ((uint32_t)__bfloat16_as_ushort(h1) << 16) | __bfloat16_as_ushort(h0);
}
__device__ __forceinline__ uint32_t pack2_lo(float a, float b) {
    __nv_bfloat16 h0 = __float2bfloat16(a), h1 = __float2bfloat16(b);
    float l0 = a - __bfloat162float(h0), l1 = b - __bfloat162float(h1);
    __nv_bfloat16 g0 = __float2bfloat16(l0), g1 = __float2bfloat16(l1);
    return ((uint32_t)__bfloat16_as_ushort(g1) << 16) | __bfloat16_as_ushort(g0);
}

// ---------------- setup: 8 blocks ----------------
__global__ __launch_bounds__(256) void setup_kernel(const unsigned char* __restrict__ mb) {
    __shared__ int flag, cnt;
    const int b = blockIdx.x, tid = threadIdx.x;
    if (tid == 0) { flag = 0; cnt = 0; }
    __syncthreads();
    int f = 0;
    for (int i = tid; i < NB*NL; i += 256)
        if ((i & 3) != 0 && mb[i] != 0) f = 1;
    if (f) atomicOr(&flag, 1);
    __syncthreads();
    const int mode = flag;
    int c = 0;
    for (int i = tid; i < NL; i += 256) {
        int pad = mode ? (mb[b*NL + i] != 0) : (((const int*)mb)[b*NL + i] != 0);
        if (!pad) c++;
    }
    atomicAdd(&cnt, c);
    __syncthreads();
    if (tid == 0) gLen[b] = cnt;
}

// ---------------- merged fp32 -> bf16 conversion ----------------
#define CN0 (NM*ND/4)
#define CN1 (3*ND*ND/4)
#define CN2 (NDFF*ND/4)
#define CN3 (ND*NDFF/4)
__global__ void conv_all(const float* __restrict__ src, const float* __restrict__ w0,
                         const float* __restrict__ w1, const float* __restrict__ w2) {
    int i = blockIdx.x * 256 + threadIdx.x;
    const float* x; __nv_bfloat16 *hi, *lo;
    if (i < CN0)                 { x = src; hi = gSrcHi;  lo = nullptr; }
    else if (i < CN0+CN1)        { i -= CN0; x = w0; hi = gWqkvHi; lo = nullptr; }
    else if (i < CN0+CN1+CN2)    { i -= CN0+CN1; x = w1; hi = gW1Hi; lo = gW1Lo; }
    else if (i < CN0+CN1+CN2+CN3){ i -= CN0+CN1+CN2; x = w2; hi = gW2Hi; lo = gW2Lo; }
    else return;
    float4 f = ((const float4*)x)[i];
    uint2 h;
    h.x = pack2_hi(f.x, f.y); h.y = pack2_hi(f.z, f.w);
    ((uint2*)hi)[i] = h;
    if (lo) {
        uint2 l;
        l.x = pack2_lo(f.x, f.y); l.y = pack2_lo(f.z, f.w);
        ((uint2*)lo)[i] = l;
    }
}

// ---------------- merged weight+bias fusion ----------------
__global__ void fuse_wb(const float* __restrict__ pw, const float* __restrict__ ow,
                        const float* __restrict__ ob, const float* __restrict__ pb) {
    int i = blockIdx.x, j = threadIdx.x;
    if (i == ND) {
        float s = pb[j];
        #pragma unroll 8
        for (int k = 0; k < ND; k++)
            s = fmaf(pw[j*ND + k], ob[k], s);
        gBc[j] = s;
        return;
    }
    float s = 0.f;
    #pragma unroll 8
    for (int k = 0; k < ND; k++)
        s = fmaf(pw[i*ND + k], ow[k*ND + j], s);
    __nv_bfloat16 h = __float2bfloat16(s);
    gWcHi[i*ND + j] = h;
    gWcLo[i*ND + j] = __float2bfloat16(s - __bfloat162float(h));
}

// ---------------- mma.sync GEMM, NPROD products ----------------
// NPROD=1: Ah*Bh              (QKV)
// NPROD=2: Ah*Bh + Ah*Bl      (proj, FF1, FF2 — A-lo dropped)
// 128x128 tile, 8 warps 4m x 2n, 2-stage K=32 pipeline, single sync/iter.
// EPI 0: QKV scatter (+bias) -> bf16 Q/K/V hi
// EPI 1: H = res + acc + bias -> hi/lo
// EPI 2: gelu(acc+bias) -> hi only
// EPI 3: out = (Chi+Clo residual) + acc + bias, padded rows zeroed, fp32
#define ATILE (128*80)
#define SMEM_P1 (2*2*ATILE)     // 40960
#define SMEM_P2 (2*3*ATILE)     // 61440

template<int EPI, int NPROD>
__global__ __launch_bounds__(256, 2) void mma_gemm(
    const __nv_bfloat16* __restrict__ Ahi,
    const __nv_bfloat16* __restrict__ Bhi, const __nv_bfloat16* __restrict__ Blo,
    const float* __restrict__ bias,
    float* __restrict__ Cf, __nv_bfloat16* __restrict__ Chi, __nv_bfloat16* __restrict__ Clo,
    const float* __restrict__ resf, int M, int N, int K)
{
    constexpr int NMAT = NPROD + 1;
    constexpr int STAGE = NMAT * ATILE;

    extern __shared__ char sm[];
    const uint32_t sb = smem_u32(sm);
    const int tid = threadIdx.x;
    const int lane = tid & 31, wid = tid >> 5;
    const int wm = wid & 3, wn = wid >> 2;
    const int bm = blockIdx.y * 128, bn = blockIdx.x * 128;

    if ((bm & (NL - 1)) >= gLen[bm >> 10]) {
        if (EPI == 3) {
            const float4 z4 = make_float4(0.f, 0.f, 0.f, 0.f);
            #pragma unroll
            for (int it = 0; it < 16; it++) {
                int u = it * 256 + tid;
                int r = u >> 5, c = (u & 31) << 2;
                *(float4*)(Cf + (size_t)(bm + r) * N + bn + c) = z4;
            }
        }
        return;
    }

    float acc[2][8][4];
    #pragma unroll
    for (int i = 0; i < 2; i++)
        #pragma unroll
        for (int j = 0; j < 8; j++)
            #pragma unroll
            for (int c = 0; c < 4; c++) acc[i][j][c] = 0.f;

    const int nt = K >> 5;

    auto prefetch = [&](int stage, int kt) {
        const int k0 = kt << 5;
        #pragma unroll
        for (int it = 0; it < NMAT * 2; it++) {
            int u = (it << 8) + tid;
            int mat = u >> 9, w = u & 511, r = w >> 2, c = w & 3;
            const __nv_bfloat16* g;
            int rb;
            if (mat == 0)      { g = Ahi; rb = bm; }
            else if (mat == 1) { g = Bhi; rb = bn; }
            else               { g = Blo; rb = bn; }
            cpasync16(sb + (uint32_t)(stage * STAGE + mat * ATILE + r * 80 + (c << 4)),
                      g + (size_t)(rb + r) * K + k0 + (c << 3));
        }
        CP_COMMIT();
    };

    auto compute = [&](int stage) {
        const uint32_t stb = sb + (uint32_t)(stage * STAGE);
        const int g = lane >> 3;
        #pragma unroll
        for (int ks = 0; ks < 2; ks++) {
            uint32_t af[2][4];
            #pragma unroll
            for (int fm = 0; fm < 2; fm++) {
                int row = wm * 32 + fm * 16 + (lane & 15);
                int chunk = ks * 2 + (lane >> 4);
                uint32_t a = stb + (uint32_t)(row * 80 + chunk * 16);
                LDSM_X4(af[fm][0], af[fm][1], af[fm][2], af[fm][3], a);
            }
            uint32_t bf_[4][4];
            #pragma unroll
            for (int bp = 0; bp < NPROD; bp++) {
                #pragma unroll
                for (int fq = 0; fq < 4; fq++) {
                    int row = wn * 64 + fq * 16 + ((g >> 1) << 3) + (lane & 7);
                    int chunk = ks * 2 + (g & 1);
                    uint32_t a = stb + (uint32_t)((1 + bp) * ATILE + row * 80 + chunk * 16);
                    LDSM_X4(bf_[fq][0], bf_[fq][1], bf_[fq][2], bf_[fq][3], a);
                }
                #pragma unroll
                for (int fm = 0; fm < 2; fm++)
                    #pragma unroll
                    for (int fn = 0; fn < 8; fn++) {
                        uint32_t b0 = bf_[fn >> 1][(fn & 1) * 2], b1 = bf_[fn >> 1][(fn & 1) * 2 + 1];
                        MMA16816(acc[fm][fn], af[fm], b0, b1);
                    }
            }
        }
    };

    prefetch(0, 0);
    for (int i = 0; i < nt; i++) {
        CP_WAIT(0);
        __syncthreads();
        if (i + 1 < nt) prefetch((i + 1) & 1, i + 1);
        compute(i & 1);
    }

    const int tq = lane >> 2, tr2 = (lane & 3) << 1;
    #pragma unroll
    for (int fm = 0; fm < 2; fm++) {
        #pragma unroll
        for (int fn = 0; fn < 8; fn++) {
            int col = bn + wn * 64 + fn * 8 + tr2;
            float b0 = __ldg(bias + col), b1 = __ldg(bias + col + 1);
            #pragma unroll
            for (int half = 0; half < 2; half++) {
                int row = bm + wm * 32 + fm * 16 + tq + half * 8;
                float v0 = acc[fm][fn][half * 2]     + b0;
                float v1 = acc[fm][fn][half * 2 + 1] + b1;
                if (EPI == 0) {
                    int t = col >> 8, h = (col & 255) >> 5, dh = col & 31;
                    int bb = row >> 10, ll = row & 1023;
                    size_t o = (((size_t)(bb * NH + h)) * NL + ll) * NDH + dh;
                    uint32_t hv = pack2_hi(v0, v1);
                    if (t == 0)      *(uint32_t*)(gQhi + o) = hv;
                    else if (t == 1) *(uint32_t*)(gKhi + o) = hv;
                    else             *(uint32_t*)(gVhi + o) = hv;
                } else if (EPI == 1) {
                    size_t o = (size_t)row * N + col;
                    v0 += __ldg(resf + o); v1 += __ldg(resf + o + 1);
                    *(uint32_t*)(Chi + o) = pack2_hi(v0, v1);
                    *(uint32_t*)(Clo + o) = pack2_lo(v0, v1);
                } else if (EPI == 2) {
                    size_t o = (size_t)row * N + col;
                    v0 = gelu_f(v0); v1 = gelu_f(v1);
                    *(uint32_t*)(Chi + o) = pack2_hi(v0, v1);
                } else {
                    size_t o = (size_t)row * N + col;
                    uint32_t rh = *(const uint32_t*)(Chi + o);
                    uint32_t rl = *(const uint32_t*)(Clo + o);
                    v0 += __bfloat162float(__ushort_as_bfloat16((unsigned short)(rh & 0xffff)))
                        + __bfloat162float(__ushort_as_bfloat16((unsigned short)(rl & 0xffff)));
                    v1 += __bfloat162float(__ushort_as_bfloat16((unsigned short)(rh >> 16)))
                        + __bfloat162float(__ushort_as_bfloat16((unsigned short)(rl >> 16)));
                    int bb = row >> 10, ll = row & 1023;
                    if (ll >= gLen[bb]) { v0 = 0.f; v1 = 0.f; }
                    *(float2*)(Cf + o) = make_float2(v0, v1);
                }
            }
        }
    }
}

// ---------------- tensor-core flash attention (hi-only QK, R12 shape) ---------------
#define AQ_B 5120            // 64 rows x 80B
#define AKV_B (2*AQ_B)       // Khi + Vhi per stage

__global__ __launch_bounds__(128) void attn_mma_kernel() {
    __shared__ __align__(16) unsigned char smem[AQ_B + 2*AKV_B];
    const uint32_t sb = smem_u32(smem);
    const uint32_t sQhi = sb;
    const uint32_t sKV0 = sb + AQ_B;

    const int tid = threadIdx.x, lane = tid & 31, wq = tid >> 5;
    const int bh = blockIdx.y, b = bh >> 3, h = bh & 7;
    const int qbase = blockIdx.x * 64;
    const int g = lane >> 3;
    const int tq = lane >> 2, tt = lane & 3;

    const int S = gLen[b];
    if (qbase >= S) return;

    const __nv_bfloat16* Qh = gQhi + (size_t)bh * NL * NDH;
    const __nv_bfloat16* Kh = gKhi + (size_t)bh * NL * NDH;
    const __nv_bfloat16* Vh = gVhi + (size_t)bh * NL * NDH;

    const float LOG2E = 1.4426950408889634f;
    const float sf = (float)S;
    const float invs_l2 = LOG2E / sf;
    const float scale_l2 = 0.1767766952966369f * LOG2E;
    const int nt = (S + 63) >> 6;

    #pragma unroll
    for (int it = 0; it < 2; it++) {
        int u = (it << 7) + tid;
        int r = u >> 2, c = u & 3;
        cpasync16(sQhi + (uint32_t)(r * 80 + (c << 4)),
                  Qh + (size_t)(qbase + r) * NDH + (c << 3));
    }
    auto loadKV = [&](int stage, int kt) {
        uint32_t base = sKV0 + (uint32_t)stage * AKV_B;
        #pragma unroll
        for (int it = 0; it < 4; it++) {
            int u = (it << 7) + tid;
            int mat = u >> 8, w = u & 255, r = w >> 2, c = w & 3;
            const __nv_bfloat16* gp = (mat == 0) ? Kh : Vh;
            cpasync16(base + (uint32_t)(mat * AQ_B + r * 80 + (c << 4)),
                      gp + (size_t)(kt + r) * NDH + (c << 3));
        }
        CP_COMMIT();
    };
    loadKV(0, 0);

    uint32_t aQh[2][4];
    float oAcc[4][4];
    #pragma unroll
    for (int i = 0; i < 4; i++)
        #pragma unroll
        for (int j = 0; j < 4; j++) oAcc[i][j] = 0.f;
    float mrow0 = -1e30f, mrow1 = -1e30f, lp0 = 0.f, lp1 = 0.f;

    const float qr0 = (float)(qbase + wq * 16 + tq);
    const float qr1 = qr0 + 8.f;

    for (int i = 0; i < nt; i++) {
        if (i + 1 < nt) { loadKV((i + 1) & 1, (i + 1) << 6); CP_WAIT(1); }
        else            { CP_WAIT(0); }
        __syncthreads();

        if (i == 0) {
            #pragma unroll
            for (int ks = 0; ks < 2; ks++) {
                uint32_t roff = (uint32_t)((wq * 16 + ((g & 1) << 3) + (lane & 7)) * 80
                                           + 32 * ks + 16 * (g >> 1));
                LDSM_X4(aQh[ks][0], aQh[ks][1], aQh[ks][2], aQh[ks][3], sQhi + roff);
            }
        }

        const uint32_t sK = sKV0 + (uint32_t)(i & 1) * AKV_B;
        const uint32_t sV = sK + AQ_B;
        const int kt = i << 6;

        float sA[8][4];
        #pragma unroll
        for (int j = 0; j < 8; j++)
            #pragma unroll
            for (int c = 0; c < 4; c++) sA[j][c] = 0.f;

        #pragma unroll
        for (int ks = 0; ks < 2; ks++) {
            #pragma unroll
            for (int jp = 0; jp < 4; jp++) {
                uint32_t kh[4];
                uint32_t roff = (uint32_t)((16 * jp + ((g >> 1) << 3) + (lane & 7)) * 80
                                           + 32 * ks + 16 * (g & 1));
                LDSM_X4(kh[0], kh[1], kh[2], kh[3], sK + roff);
                MMA16816(sA[2*jp],     aQh[ks], kh[0], kh[1]);
                MMA16816(sA[2*jp + 1], aQh[ks], kh[2], kh[3]);
            }
        }

        float x[8][4];
        float tmax0 = -1e30f, tmax1 = -1e30f;
        #pragma unroll
        for (int j = 0; j < 8; j++) {
            int kc = kt + 8 * j + 2 * tt;
            float k0f = (float)kc, k1f = k0f + 1.f;
            float b00 = (kc     < S) ? LOG2E - fabsf(qr0 - k0f) * invs_l2 : -1e30f;
            float b01 = (kc + 1 < S) ? LOG2E - fabsf(qr0 - k1f) * invs_l2 : -1e30f;
            float b10 = (kc     < S) ? LOG2E - fabsf(qr1 - k0f) * invs_l2 : -1e30f;
            float b11 = (kc + 1 < S) ? LOG2E - fabsf(qr1 - k1f) * invs_l2 : -1e30f;
            x[j][0] = fmaf(sA[j][0], scale_l2, b00);
            x[j][1] = fmaf(sA[j][1], scale_l2, b01);
            x[j][2] = fmaf(sA[j][2], scale_l2, b10);
            x[j][3] = fmaf(sA[j][3], scale_l2, b11);
            tmax0 = fmaxf(tmax0, fmaxf(x[j][0], x[j][1]));
            tmax1 = fmaxf(tmax1, fmaxf(x[j][2], x[j][3]));
        }
        tmax0 = fmaxf(tmax0, __shfl_xor_sync(0xffffffff, tmax0, 1));
        tmax0 = fmaxf(tmax0, __shfl_xor_sync(0xffffffff, tmax0, 2));
        tmax1 = fmaxf(tmax1, __shfl_xor_sync(0xffffffff, tmax1, 1));
        tmax1 = fmaxf(tmax1, __shfl_xor_sync(0xffffffff, tmax1, 2));
        float mn0 = fmaxf(mrow0, tmax0), mn1 = fmaxf(mrow1, tmax1);
        float corr0 = exp2f(mrow0 - mn0), corr1 = exp2f(mrow1 - mn1);
        mrow0 = mn0; mrow1 = mn1;
        lp0 *= corr0; lp1 *= corr1;
        #pragma unroll
        for (int nf = 0; nf < 4; nf++) {
            oAcc[nf][0] *= corr0; oAcc[nf][1] *= corr0;
            oAcc[nf][2] *= corr1; oAcc[nf][3] *= corr1;
        }

        uint32_t aP[4][4];
        #pragma unroll
        for (int j = 0; j < 8; j++) {
            float p0 = exp2f(x[j][0] - mn0), p1 = exp2f(x[j][1] - mn0);
            float p2 = exp2f(x[j][2] - mn1), p3 = exp2f(x[j][3] - mn1);
            lp0 += p0 + p1; lp1 += p2 + p3;
            int jp = j >> 1, s2 = (j & 1) << 1;
            aP[jp][s2]     = pack2_hi(p0, p1);
            aP[jp][s2 + 1] = pack2_hi(p2, p3);
        }

        #pragma unroll
        for (int jp = 0; jp < 4; jp++) {
            uint32_t bv[8];
            uint32_t roff = (uint32_t)((16 * jp + ((g & 1) << 3) + (lane & 7)) * 80
                                       + 16 * (g >> 1));
            LDSM_X4_T(bv[0], bv[1], bv[2], bv[3], sV + roff);
            LDSM_X4_T(bv[4], bv[5], bv[6], bv[7], sV + roff + 32);
            MMA16816(oAcc[0], aP[jp], bv[0], bv[1]);
            MMA16816(oAcc[1], aP[jp], bv[2], bv[3]);
            MMA16816(oAcc[2], aP[jp], bv[4], bv[5]);
            MMA16816(oAcc[3], aP[jp], bv[6], bv[7]);
        }
        __syncthreads();
    }

    lp0 += __shfl_xor_sync(0xffffffff, lp0, 1);
    lp0 += __shfl_xor_sync(0xffffffff, lp0, 2);
    lp1 += __shfl_xor_sync(0xffffffff, lp1, 1);
    lp1 += __shfl_xor_sync(0xffffffff, lp1, 2);
    float inv0 = 1.f / lp0, inv1 = 1.f / lp1;
    int r0 = qbase + wq * 16 + tq, r1 = r0 + 8;
    #pragma unroll
    for (int nf = 0; nf < 4; nf++) {
        int dh = 8 * nf + 2 * tt;
        size_t o0 = ((size_t)(b * NL + r0)) * ND + h * NDH + dh;
        size_t o1 = ((size_t)(b * NL + r1)) * ND + h * NDH + dh;
        *(uint32_t*)(gCtxHi + o0) = pack2_hi(oAcc[nf][0] * inv0, oAcc[nf][1] * inv0);
        *(uint32_t*)(gCtxHi + o1) = pack2_hi(oAcc[nf][2] * inv1, oAcc[nf][3] * inv1);
    }
}

// ---------------- launcher ----------------
extern "C" void kernel_launch(void* const* d_in, const int* in_sizes, int n_in,
                              void* d_out, int out_size) {
    const float* src       = (const float*)d_in[0];
    const unsigned char* mask = (const unsigned char*)d_in[1];
    const float* in_proj_w = (const float*)d_in[2];
    const float* in_proj_b = (const float*)d_in[3];
    const float* out_w     = (const float*)d_in[4];
    const float* out_b     = (const float*)d_in[5];
    const float* proj_w    = (const float*)d_in[6];
    const float* proj_b    = (const float*)d_in[7];
    const float* ff1_w     = (const float*)d_in[8];
    const float* ff1_b     = (const float*)d_in[9];
    const float* ff2_w     = (const float*)d_in[10];
    const float* ff2_b     = (const float*)d_in[11];
    float* out = (float*)d_out;

    cudaFuncSetAttribute((void*)mma_gemm<0,1>, cudaFuncAttributeMaxDynamicSharedMemorySize, SMEM_P1);
    cudaFuncSetAttribute((void*)mma_gemm<1,2>, cudaFuncAttributeMaxDynamicSharedMemorySize, SMEM_P2);
    cudaFuncSetAttribute((void*)mma_gemm<2,2>, cudaFuncAttributeMaxDynamicSharedMemorySize, SMEM_P2);
    cudaFuncSetAttribute((void*)mma_gemm<3,2>, cudaFuncAttributeMaxDynamicSharedMemorySize, SMEM_P2);

    float *pBc;
    __nv_bfloat16 *pSrcHi, *pCtxHi, *pHHi, *pHLo, *pFFHi;
    __nv_bfloat16 *pWqkvHi, *pWcHi, *pWcLo, *pW1Hi, *pW1Lo, *pW2Hi, *pW2Lo;
    cudaGetSymbolAddress((void**)&pBc, gBc);
    cudaGetSymbolAddress((void**)&pSrcHi, gSrcHi);
    cudaGetSymbolAddress((void**)&pCtxHi, gCtxHi);
    cudaGetSymbolAddress((void**)&pHHi, gHHi);   cudaGetSymbolAddress((void**)&pHLo, gHLo);
    cudaGetSymbolAddress((void**)&pFFHi, gFFHi);
    cudaGetSymbolAddress((void**)&pWqkvHi, gWqkvHi);
    cudaGetSymbolAddress((void**)&pWcHi, gWcHi); cudaGetSymbolAddress((void**)&pWcLo, gWcLo);
    cudaGetSymbolAddress((void**)&pW1Hi, gW1Hi); cudaGetSymbolAddress((void**)&pW1Lo, gW1Lo);
    cudaGetSymbolAddress((void**)&pW2Hi, gW2Hi); cudaGetSymbolAddress((void**)&pW2Lo, gW2Lo);

    setup_kernel<<<NB, 256>>>(mask);
    conv_all<<<(CN0+CN1+CN2+CN3 + 255)/256, 256>>>(src, in_proj_w, ff1_w, ff2_w);
    fuse_wb<<<ND + 1, ND>>>(proj_w, out_w, out_b, proj_b);

    // QKV = src @ in_proj_w^T + b (1 product) -> bf16 Q/K/V
    mma_gemm<0,1><<<dim3(6, 64), 256, SMEM_P1>>>(pSrcHi, pWqkvHi, nullptr,
        in_proj_b, nullptr, nullptr, nullptr, nullptr, NM, 3*ND, ND);
    // tensor-core attention -> ctx hi
    attn_mma_kernel<<<dim3(16, 64), 128>>>();
    // H = src + ctx_h @ (Wc_h + Wc_l)^T + bc -> hi/lo
    mma_gemm<1,2><<<dim3(2, 64), 256, SMEM_P2>>>(pCtxHi, pWcHi, pWcLo,
        pBc, nullptr, pHHi, pHLo, src, NM, ND, ND);
    // ff = gelu(H_h @ (W1_h + W1_l)^T + b1) -> hi only
    mma_gemm<2,2><<<dim3(16, 64), 256, SMEM_P2>>>(pHHi, pW1Hi, pW1Lo,
        ff1_b, nullptr, pFFHi, nullptr, nullptr, NM, NDFF, ND);
    // out = (Hhi+Hlo) + ff_h @ (W2_h + W2_l)^T + b2, padded rows zeroed
    mma_gemm<3,2><<<dim3(2, 64), 256, SMEM_P2>>>(pFFHi, pW2Hi, pW2Lo,
        ff2_b, out, pHHi, pHLo, nullptr, NM, ND, NDFF);
}

// round 15
// speedup vs baseline: 1.3697x; 1.0068x over previous
#include <cuda_runtime.h>
#include <cuda_bf16.h>
#include <math.h>
#include <stdint.h>

#define NB 8
#define NL 1024
#define ND 256
#define NH 8
#define NDH 32
#define NDFF 2048
#define NM (NB*NL)

// ---------------- scratch (device globals; allocation-free, zero-init) ----------------
__device__ __nv_bfloat16 gQhi[64*NL*NDH];
__device__ __nv_bfloat16 gKhi[64*NL*NDH];
__device__ __nv_bfloat16 gVhi[64*NL*NDH];
__device__ __nv_bfloat16 gSrcHi[NM*ND];
__device__ __nv_bfloat16 gCtxHi[NM*ND];
__device__ __nv_bfloat16 gHHi[NM*ND], gHLo[NM*ND];
__device__ __nv_bfloat16 gFFHi[(size_t)NM*NDFF];
__device__ __nv_bfloat16 gWqkvHi[3*ND*ND];
__device__ __nv_bfloat16 gWcHi[ND*ND],   gWcLo[ND*ND];
__device__ __nv_bfloat16 gW1Hi[NDFF*ND], gW1Lo[NDFF*ND];
__device__ __nv_bfloat16 gW2Hi[ND*NDFF], gW2Lo[ND*NDFF];
__device__ float gBc[ND];
__device__ int   gLen[NB];

// ---------------- helpers ----------------
__device__ __forceinline__ uint32_t smem_u32(const void* p) {
    uint32_t a;
    asm("{ .reg .u64 t; cvta.to.shared.u64 t, %1; cvt.u32.u64 %0, t; }" : "=r"(a) : "l"(p));
    return a;
}
__device__ __forceinline__ void cpasync16(uint32_t saddr, const void* gaddr) {
    asm volatile("cp.async.cg.shared.global [%0], [%1], 16;" :: "r"(saddr), "l"(gaddr) : "memory");
}
#define CP_COMMIT() asm volatile("cp.async.commit_group;" ::: "memory")
#define CP_WAIT(n)  asm volatile("cp.async.wait_group %0;" :: "n"(n) : "memory")

#define LDSM_X4(r0, r1, r2, r3, addr) \
    asm volatile("ldmatrix.sync.aligned.m8n8.x4.shared.b16 {%0,%1,%2,%3}, [%4];" \
        : "=r"(r0), "=r"(r1), "=r"(r2), "=r"(r3) : "r"(addr))
#define LDSM_X4_T(r0, r1, r2, r3, addr) \
    asm volatile("ldmatrix.sync.aligned.m8n8.x4.trans.shared.b16 {%0,%1,%2,%3}, [%4];" \
        : "=r"(r0), "=r"(r1), "=r"(r2), "=r"(r3) : "r"(addr))

#define MMA16816(d, a, b0, b1) \
    asm volatile("mma.sync.aligned.m16n8k16.row.col.f32.bf16.bf16.f32 " \
        "{%0,%1,%2,%3}, {%4,%5,%6,%7}, {%8,%9}, {%0,%1,%2,%3};" \
        : "+f"((d)[0]), "+f"((d)[1]), "+f"((d)[2]), "+f"((d)[3]) \
        : "r"((a)[0]), "r"((a)[1]), "r"((a)[2]), "r"((a)[3]), "r"(b0), "r"(b1))

__device__ __forceinline__ float gelu_f(float x) {
    return 0.5f * x * (1.f + erff(x * 0.7071067811865475f));
}
__device__ __forceinline__ uint32_t pack2_hi(float a, float b) {
    __nv_bfloat16 h0 = __float2bfloat16(a), h1 = __float2bfloat16(b);
    return ((uint32_t)__bfloat16_as_ushort(h1) << 16) | __bfloat16_as_ushort(h0);
}
__device__ __forceinline__ uint32_t pack2_lo(float a, float b) {
    __nv_bfloat16 h0 = __float2bfloat16(a), h1 = __float2bfloat16(b);
    float l0 = a - __bfloat162float(h0), l1 = b - __bfloat162float(h1);
    __nv_bfloat16 g0 = __float2bfloat16(l0), g1 = __float2bfloat16(l1);
    return ((uint32_t)__bfloat16_as_ushort(g1) << 16) | __bfloat16_as_ushort(g0);
}

// ---------------- setup: 8 blocks ----------------
__global__ __launch_bounds__(256) void setup_kernel(const unsigned char* __restrict__ mb) {
    __shared__ int flag, cnt;
    const int b = blockIdx.x, tid = threadIdx.x;
    if (tid == 0) { flag = 0; cnt = 0; }
    __syncthreads();
    int f = 0;
    for (int i = tid; i < NB*NL; i += 256)
        if ((i & 3) != 0 && mb[i] != 0) f = 1;
    if (f) atomicOr(&flag, 1);
    __syncthreads();
    const int mode = flag;
    int c = 0;
    for (int i = tid; i < NL; i += 256) {
        int pad = mode ? (mb[b*NL + i] != 0) : (((const int*)mb)[b*NL + i] != 0);
        if (!pad) c++;
    }
    atomicAdd(&cnt, c);
    __syncthreads();
    if (tid == 0) gLen[b] = cnt;
}

// ---------------- merged fp32 -> bf16 conversion ----------------
#define CN0 (NM*ND/4)
#define CN1 (3*ND*ND/4)
#define CN2 (NDFF*ND/4)
#define CN3 (ND*NDFF/4)
__global__ void conv_all(const float* __restrict__ src, const float* __restrict__ w0,
                         const float* __restrict__ w1, const float* __restrict__ w2) {
    int i = blockIdx.x * 256 + threadIdx.x;
    const float* x; __nv_bfloat16 *hi, *lo;
    if (i < CN0)                 { x = src; hi = gSrcHi;  lo = nullptr; }
    else if (i < CN0+CN1)        { i -= CN0; x = w0; hi = gWqkvHi; lo = nullptr; }
    else if (i < CN0+CN1+CN2)    { i -= CN0+CN1; x = w1; hi = gW1Hi; lo = gW1Lo; }
    else if (i < CN0+CN1+CN2+CN3){ i -= CN0+CN1+CN2; x = w2; hi = gW2Hi; lo = gW2Lo; }
    else return;
    float4 f = ((const float4*)x)[i];
    uint2 h;
    h.x = pack2_hi(f.x, f.y); h.y = pack2_hi(f.z, f.w);
    ((uint2*)hi)[i] = h;
    if (lo) {
        uint2 l;
        l.x = pack2_lo(f.x, f.y); l.y = pack2_lo(f.z, f.w);
        ((uint2*)lo)[i] = l;
    }
}

// ---------------- merged weight+bias fusion ----------------
__global__ void fuse_wb(const float* __restrict__ pw, const float* __restrict__ ow,
                        const float* __restrict__ ob, const float* __restrict__ pb) {
    int i = blockIdx.x, j = threadIdx.x;
    if (i == ND) {
        float s = pb[j];
        #pragma unroll 8
        for (int k = 0; k < ND; k++)
            s = fmaf(pw[j*ND + k], ob[k], s);
        gBc[j] = s;
        return;
    }
    float s = 0.f;
    #pragma unroll 8
    for (int k = 0; k < ND; k++)
        s = fmaf(pw[i*ND + k], ow[k*ND + j], s);
    __nv_bfloat16 h = __float2bfloat16(s);
    gWcHi[i*ND + j] = h;
    gWcLo[i*ND + j] = __float2bfloat16(s - __bfloat162float(h));
}

// ---------------- mma.sync GEMM, NPROD products, 3-stage pipeline ----------------
// NPROD=1: Ah*Bh              (QKV)
// NPROD=2: Ah*Bh + Ah*Bl      (proj, FF1, FF2)
// 128x128 tile, 8 warps 4m x 2n, K=32 stages, 3-deep cp.async, single sync/iter.
#define ATILE (128*80)
#define SMEM_P1 (3*2*ATILE)     // 61440
#define SMEM_P2 (3*3*ATILE)     // 92160

template<int EPI, int NPROD>
__global__ __launch_bounds__(256, 2) void mma_gemm(
    const __nv_bfloat16* __restrict__ Ahi,
    const __nv_bfloat16* __restrict__ Bhi, const __nv_bfloat16* __restrict__ Blo,
    const float* __restrict__ bias,
    float* __restrict__ Cf, __nv_bfloat16* __restrict__ Chi, __nv_bfloat16* __restrict__ Clo,
    const float* __restrict__ resf, int M, int N, int K)
{
    constexpr int NMAT = NPROD + 1;
    constexpr int STAGE = NMAT * ATILE;

    extern __shared__ char sm[];
    const uint32_t sb = smem_u32(sm);
    const int tid = threadIdx.x;
    const int lane = tid & 31, wid = tid >> 5;
    const int wm = wid & 3, wn = wid >> 2;
    const int bm = blockIdx.y * 128, bn = blockIdx.x * 128;

    if ((bm & (NL - 1)) >= gLen[bm >> 10]) {
        if (EPI == 3) {
            const float4 z4 = make_float4(0.f, 0.f, 0.f, 0.f);
            #pragma unroll
            for (int it = 0; it < 16; it++) {
                int u = it * 256 + tid;
                int r = u >> 5, c = (u & 31) << 2;
                *(float4*)(Cf + (size_t)(bm + r) * N + bn + c) = z4;
            }
        }
        return;
    }

    float acc[2][8][4];
    #pragma unroll
    for (int i = 0; i < 2; i++)
        #pragma unroll
        for (int j = 0; j < 8; j++)
            #pragma unroll
            for (int c = 0; c < 4; c++) acc[i][j][c] = 0.f;

    const int nt = K >> 5;

    auto prefetch = [&](int stage, int kt) {
        const int k0 = kt << 5;
        #pragma unroll
        for (int it = 0; it < NMAT * 2; it++) {
            int u = (it << 8) + tid;
            int mat = u >> 9, w = u & 511, r = w >> 2, c = w & 3;
            const __nv_bfloat16* g;
            int rb;
            if (mat == 0)      { g = Ahi; rb = bm; }
            else if (mat == 1) { g = Bhi; rb = bn; }
            else               { g = Blo; rb = bn; }
            cpasync16(sb + (uint32_t)(stage * STAGE + mat * ATILE + r * 80 + (c << 4)),
                      g + (size_t)(rb + r) * K + k0 + (c << 3));
        }
        CP_COMMIT();
    };

    auto compute = [&](int stage) {
        const uint32_t stb = sb + (uint32_t)(stage * STAGE);
        const int g = lane >> 3;
        #pragma unroll
        for (int ks = 0; ks < 2; ks++) {
            uint32_t af[2][4];
            #pragma unroll
            for (int fm = 0; fm < 2; fm++) {
                int row = wm * 32 + fm * 16 + (lane & 15);
                int chunk = ks * 2 + (lane >> 4);
                uint32_t a = stb + (uint32_t)(row * 80 + chunk * 16);
                LDSM_X4(af[fm][0], af[fm][1], af[fm][2], af[fm][3], a);
            }
            uint32_t bf_[4][4];
            #pragma unroll
            for (int bp = 0; bp < NPROD; bp++) {
                #pragma unroll
                for (int fq = 0; fq < 4; fq++) {
                    int row = wn * 64 + fq * 16 + ((g >> 1) << 3) + (lane & 7);
                    int chunk = ks * 2 + (g & 1);
                    uint32_t a = stb + (uint32_t)((1 + bp) * ATILE + row * 80 + chunk * 16);
                    LDSM_X4(bf_[fq][0], bf_[fq][1], bf_[fq][2], bf_[fq][3], a);
                }
                #pragma unroll
                for (int fm = 0; fm < 2; fm++)
                    #pragma unroll
                    for (int fn = 0; fn < 8; fn++) {
                        uint32_t b0 = bf_[fn >> 1][(fn & 1) * 2], b1 = bf_[fn >> 1][(fn & 1) * 2 + 1];
                        MMA16816(acc[fm][fn], af[fm], b0, b1);
                    }
            }
        }
    };

    // 3-stage pipeline: wait(1) needs only stage i complete; stage i+1 rides
    // through compute(i). The sync retires compute(i-1), freeing buffer (i+2)%3.
    prefetch(0, 0);
    prefetch(1, 1);
    int st = 0, stp = 2;   // compute stage, prefetch stage
    for (int i = 0; i < nt; i++) {
        CP_WAIT(1);
        __syncthreads();
        if (i + 2 < nt) prefetch(stp, i + 2);
        else CP_COMMIT();
        compute(st);
        st = (st == 2) ? 0 : st + 1;
        stp = (stp == 2) ? 0 : stp + 1;
    }

    const int tq = lane >> 2, tr2 = (lane & 3) << 1;
    #pragma unroll
    for (int fm = 0; fm < 2; fm++) {
        #pragma unroll
        for (int fn = 0; fn < 8; fn++) {
            int col = bn + wn * 64 + fn * 8 + tr2;
            float b0 = __ldg(bias + col), b1 = __ldg(bias + col + 1);
            #pragma unroll
            for (int half = 0; half < 2; half++) {
                int row = bm + wm * 32 + fm * 16 + tq + half * 8;
                float v0 = acc[fm][fn][half * 2]     + b0;
                float v1 = acc[fm][fn][half * 2 + 1] + b1;
                if (EPI == 0) {
                    int t = col >> 8, h = (col & 255) >> 5, dh = col & 31;
                    int bb = row >> 10, ll = row & 1023;
                    size_t o = (((size_t)(bb * NH + h)) * NL + ll) * NDH + dh;
                    uint32_t hv = pack2_hi(v0, v1);
                    if (t == 0)      *(uint32_t*)(gQhi + o) = hv;
                    else if (t == 1) *(uint32_t*)(gKhi + o) = hv;
                    else             *(uint32_t*)(gVhi + o) = hv;
                } else if (EPI == 1) {
                    size_t o = (size_t)row * N + col;
                    v0 += __ldg(resf + o); v1 += __ldg(resf + o + 1);
                    *(uint32_t*)(Chi + o) = pack2_hi(v0, v1);
                    *(uint32_t*)(Clo + o) = pack2_lo(v0, v1);
                } else if (EPI == 2) {
                    size_t o = (size_t)row * N + col;
                    v0 = gelu_f(v0); v1 = gelu_f(v1);
                    *(uint32_t*)(Chi + o) = pack2_hi(v0, v1);
                } else {
                    size_t o = (size_t)row * N + col;
                    uint32_t rh = *(const uint32_t*)(Chi + o);
                    uint32_t rl = *(const uint32_t*)(Clo + o);
                    v0 += __bfloat162float(__ushort_as_bfloat16((unsigned short)(rh & 0xffff)))
                        + __bfloat162float(__ushort_as_bfloat16((unsigned short)(rl & 0xffff)));
                    v1 += __bfloat162float(__ushort_as_bfloat16((unsigned short)(rh >> 16)))
                        + __bfloat162float(__ushort_as_bfloat16((unsigned short)(rl >> 16)));
                    int bb = row >> 10, ll = row & 1023;
                    if (ll >= gLen[bb]) { v0 = 0.f; v1 = 0.f; }
                    *(float2*)(Cf + o) = make_float2(v0, v1);
                }
            }
        }
    }
}

// ---------------- tensor-core flash attention (hi-only QK, R12 shape) ---------------
#define AQ_B 5120            // 64 rows x 80B
#define AKV_B (2*AQ_B)       // Khi + Vhi per stage

__global__ __launch_bounds__(128) void attn_mma_kernel() {
    __shared__ __align__(16) unsigned char smem[AQ_B + 2*AKV_B];
    const uint32_t sb = smem_u32(smem);
    const uint32_t sQhi = sb;
    const uint32_t sKV0 = sb + AQ_B;

    const int tid = threadIdx.x, lane = tid & 31, wq = tid >> 5;
    const int bh = blockIdx.y, b = bh >> 3, h = bh & 7;
    const int qbase = blockIdx.x * 64;
    const int g = lane >> 3;
    const int tq = lane >> 2, tt = lane & 3;

    const int S = gLen[b];
    if (qbase >= S) return;

    const __nv_bfloat16* Qh = gQhi + (size_t)bh * NL * NDH;
    const __nv_bfloat16* Kh = gKhi + (size_t)bh * NL * NDH;
    const __nv_bfloat16* Vh = gVhi + (size_t)bh * NL * NDH;

    const float LOG2E = 1.4426950408889634f;
    const float sf = (float)S;
    const float invs_l2 = LOG2E / sf;
    const float scale_l2 = 0.1767766952966369f * LOG2E;
    const int nt = (S + 63) >> 6;

    #pragma unroll
    for (int it = 0; it < 2; it++) {
        int u = (it << 7) + tid;
        int r = u >> 2, c = u & 3;
        cpasync16(sQhi + (uint32_t)(r * 80 + (c << 4)),
                  Qh + (size_t)(qbase + r) * NDH + (c << 3));
    }
    auto loadKV = [&](int stage, int kt) {
        uint32_t base = sKV0 + (uint32_t)stage * AKV_B;
        #pragma unroll
        for (int it = 0; it < 4; it++) {
            int u = (it << 7) + tid;
            int mat = u >> 8, w = u & 255, r = w >> 2, c = w & 3;
            const __nv_bfloat16* gp = (mat == 0) ? Kh : Vh;
            cpasync16(base + (uint32_t)(mat * AQ_B + r * 80 + (c << 4)),
                      gp + (size_t)(kt + r) * NDH + (c << 3));
        }
        CP_COMMIT();
    };
    loadKV(0, 0);

    uint32_t aQh[2][4];
    float oAcc[4][4];
    #pragma unroll
    for (int i = 0; i < 4; i++)
        #pragma unroll
        for (int j = 0; j < 4; j++) oAcc[i][j] = 0.f;
    float mrow0 = -1e30f, mrow1 = -1e30f, lp0 = 0.f, lp1 = 0.f;

    const float qr0 = (float)(qbase + wq * 16 + tq);
    const float qr1 = qr0 + 8.f;

    for (int i = 0; i < nt; i++) {
        if (i + 1 < nt) { loadKV((i + 1) & 1, (i + 1) << 6); CP_WAIT(1); }
        else            { CP_WAIT(0); }
        __syncthreads();

        if (i == 0) {
            #pragma unroll
            for (int ks = 0; ks < 2; ks++) {
                uint32_t roff = (uint32_t)((wq * 16 + ((g & 1) << 3) + (lane & 7)) * 80
                                           + 32 * ks + 16 * (g >> 1));
                LDSM_X4(aQh[ks][0], aQh[ks][1], aQh[ks][2], aQh[ks][3], sQhi + roff);
            }
        }

        const uint32_t sK = sKV0 + (uint32_t)(i & 1) * AKV_B;
        const uint32_t sV = sK + AQ_B;
        const int kt = i << 6;

        float sA[8][4];
        #pragma unroll
        for (int j = 0; j < 8; j++)
            #pragma unroll
            for (int c = 0; c < 4; c++) sA[j][c] = 0.f;

        #pragma unroll
        for (int ks = 0; ks < 2; ks++) {
            #pragma unroll
            for (int jp = 0; jp < 4; jp++) {
                uint32_t kh[4];
                uint32_t roff = (uint32_t)((16 * jp + ((g >> 1) << 3) + (lane & 7)) * 80
                                           + 32 * ks + 16 * (g & 1));
                LDSM_X4(kh[0], kh[1], kh[2], kh[3], sK + roff);
                MMA16816(sA[2*jp],     aQh[ks], kh[0], kh[1]);
                MMA16816(sA[2*jp + 1], aQh[ks], kh[2], kh[3]);
            }
        }

        float x[8][4];
        float tmax0 = -1e30f, tmax1 = -1e30f;
        #pragma unroll
        for (int j = 0; j < 8; j++) {
            int kc = kt + 8 * j + 2 * tt;
            float k0f = (float)kc, k1f = k0f + 1.f;
            float b00 = (kc     < S) ? LOG2E - fabsf(qr0 - k0f) * invs_l2 : -1e30f;
            float b01 = (kc + 1 < S) ? LOG2E - fabsf(qr0 - k1f) * invs_l2 : -1e30f;
            float b10 = (kc     < S) ? LOG2E - fabsf(qr1 - k0f) * invs_l2 : -1e30f;
            float b11 = (kc + 1 < S) ? LOG2E - fabsf(qr1 - k1f) * invs_l2 : -1e30f;
            x[j][0] = fmaf(sA[j][0], scale_l2, b00);
            x[j][1] = fmaf(sA[j][1], scale_l2, b01);
            x[j][2] = fmaf(sA[j][2], scale_l2, b10);
            x[j][3] = fmaf(sA[j][3], scale_l2, b11);
            tmax0 = fmaxf(tmax0, fmaxf(x[j][0], x[j][1]));
            tmax1 = fmaxf(tmax1, fmaxf(x[j][2], x[j][3]));
        }
        tmax0 = fmaxf(tmax0, __shfl_xor_sync(0xffffffff, tmax0, 1));
        tmax0 = fmaxf(tmax0, __shfl_xor_sync(0xffffffff, tmax0, 2));
        tmax1 = fmaxf(tmax1, __shfl_xor_sync(0xffffffff, tmax1, 1));
        tmax1 = fmaxf(tmax1, __shfl_xor_sync(0xffffffff, tmax1, 2));
        float mn0 = fmaxf(mrow0, tmax0), mn1 = fmaxf(mrow1, tmax1);
        float corr0 = exp2f(mrow0 - mn0), corr1 = exp2f(mrow1 - mn1);
        mrow0 = mn0; mrow1 = mn1;
        lp0 *= corr0; lp1 *= corr1;
        #pragma unroll
        for (int nf = 0; nf < 4; nf++) {
            oAcc[nf][0] *= corr0; oAcc[nf][1] *= corr0;
            oAcc[nf][2] *= corr1; oAcc[nf][3] *= corr1;
        }

        uint32_t aP[4][4];
        #pragma unroll
        for (int j = 0; j < 8; j++) {
            float p0 = exp2f(x[j][0] - mn0), p1 = exp2f(x[j][1] - mn0);
            float p2 = exp2f(x[j][2] - mn1), p3 = exp2f(x[j][3] - mn1);
            lp0 += p0 + p1; lp1 += p2 + p3;
            int jp = j >> 1, s2 = (j & 1) << 1;
            aP[jp][s2]     = pack2_hi(p0, p1);
            aP[jp][s2 + 1] = pack2_hi(p2, p3);
        }

        #pragma unroll
        for (int jp = 0; jp < 4; jp++) {
            uint32_t bv[8];
            uint32_t roff = (uint32_t)((16 * jp + ((g & 1) << 3) + (lane & 7)) * 80
                                       + 16 * (g >> 1));
            LDSM_X4_T(bv[0], bv[1], bv[2], bv[3], sV + roff);
            LDSM_X4_T(bv[4], bv[5], bv[6], bv[7], sV + roff + 32);
            MMA16816(oAcc[0], aP[jp], bv[0], bv[1]);
            MMA16816(oAcc[1], aP[jp], bv[2], bv[3]);
            MMA16816(oAcc[2], aP[jp], bv[4], bv[5]);
            MMA16816(oAcc[3], aP[jp], bv[6], bv[7]);
        }
        __syncthreads();
    }

    lp0 += __shfl_xor_sync(0xffffffff, lp0, 1);
    lp0 += __shfl_xor_sync(0xffffffff, lp0, 2);
    lp1 += __shfl_xor_sync(0xffffffff, lp1, 1);
    lp1 += __shfl_xor_sync(0xffffffff, lp1, 2);
    float inv0 = 1.f / lp0, inv1 = 1.f / lp1;
    int r0 = qbase + wq * 16 + tq, r1 = r0 + 8;
    #pragma unroll
    for (int nf = 0; nf < 4; nf++) {
        int dh = 8 * nf + 2 * tt;
        size_t o0 = ((size_t)(b * NL + r0)) * ND + h * NDH + dh;
        size_t o1 = ((size_t)(b * NL + r1)) * ND + h * NDH + dh;
        *(uint32_t*)(gCtxHi + o0) = pack2_hi(oAcc[nf][0] * inv0, oAcc[nf][1] * inv0);
        *(uint32_t*)(gCtxHi + o1) = pack2_hi(oAcc[nf][2] * inv1, oAcc[nf][3] * inv1);
    }
}

// ---------------- launcher ----------------
extern "C" void kernel_launch(void* const* d_in, const int* in_sizes, int n_in,
                              void* d_out, int out_size) {
    const float* src       = (const float*)d_in[0];
    const unsigned char* mask = (const unsigned char*)d_in[1];
    const float* in_proj_w = (const float*)d_in[2];
    const float* in_proj_b = (const float*)d_in[3];
    const float* out_w     = (const float*)d_in[4];
    const float* out_b     = (const float*)d_in[5];
    const float* proj_w    = (const float*)d_in[6];
    const float* proj_b    = (const float*)d_in[7];
    const float* ff1_w     = (const float*)d_in[8];
    const float* ff1_b     = (const float*)d_in[9];
    const float* ff2_w     = (const float*)d_in[10];
    const float* ff2_b     = (const float*)d_in[11];
    float* out = (float*)d_out;

    cudaFuncSetAttribute((void*)mma_gemm<0,1>, cudaFuncAttributeMaxDynamicSharedMemorySize, SMEM_P1);
    cudaFuncSetAttribute((void*)mma_gemm<1,2>, cudaFuncAttributeMaxDynamicSharedMemorySize, SMEM_P2);
    cudaFuncSetAttribute((void*)mma_gemm<2,2>, cudaFuncAttributeMaxDynamicSharedMemorySize, SMEM_P2);
    cudaFuncSetAttribute((void*)mma_gemm<3,2>, cudaFuncAttributeMaxDynamicSharedMemorySize, SMEM_P2);

    float *pBc;
    __nv_bfloat16 *pSrcHi, *pCtxHi, *pHHi, *pHLo, *pFFHi;
    __nv_bfloat16 *pWqkvHi, *pWcHi, *pWcLo, *pW1Hi, *pW1Lo, *pW2Hi, *pW2Lo;
    cudaGetSymbolAddress((void**)&pBc, gBc);
    cudaGetSymbolAddress((void**)&pSrcHi, gSrcHi);
    cudaGetSymbolAddress((void**)&pCtxHi, gCtxHi);
    cudaGetSymbolAddress((void**)&pHHi, gHHi);   cudaGetSymbolAddress((void**)&pHLo, gHLo);
    cudaGetSymbolAddress((void**)&pFFHi, gFFHi);
    cudaGetSymbolAddress((void**)&pWqkvHi, gWqkvHi);
    cudaGetSymbolAddress((void**)&pWcHi, gWcHi); cudaGetSymbolAddress((void**)&pWcLo, gWcLo);
    cudaGetSymbolAddress((void**)&pW1Hi, gW1Hi); cudaGetSymbolAddress((void**)&pW1Lo, gW1Lo);
    cudaGetSymbolAddress((void**)&pW2Hi, gW2Hi); cudaGetSymbolAddress((void**)&pW2Lo, gW2Lo);

    setup_kernel<<<NB, 256>>>(mask);
    conv_all<<<(CN0+CN1+CN2+CN3 + 255)/256, 256>>>(src, in_proj_w, ff1_w, ff2_w);
    fuse_wb<<<ND + 1, ND>>>(proj_w, out_w, out_b, proj_b);

    // QKV = src @ in_proj_w^T + b (1 product) -> bf16 Q/K/V
    mma_gemm<0,1><<<dim3(6, 64), 256, SMEM_P1>>>(pSrcHi, pWqkvHi, nullptr,
        in_proj_b, nullptr, nullptr, nullptr, nullptr, NM, 3*ND, ND);
    // tensor-core attention -> ctx hi
    attn_mma_kernel<<<dim3(16, 64), 128>>>();
    // H = src + ctx_h @ (Wc_h + Wc_l)^T + bc -> hi/lo
    mma_gemm<1,2><<<dim3(2, 64), 256, SMEM_P2>>>(pCtxHi, pWcHi, pWcLo,
        pBc, nullptr, pHHi, pHLo, src, NM, ND, ND);
    // ff = gelu(H_h @ (W1_h + W1_l)^T + b1) -> hi only
    mma_gemm<2,2><<<dim3(16, 64), 256, SMEM_P2>>>(pHHi, pW1Hi, pW1Lo,
        ff1_b, nullptr, pFFHi, nullptr, nullptr, NM, NDFF, ND);
    // out = (Hhi+Hlo) + ff_h @ (W2_h + W2_l)^T + b2, padded rows zeroed
    mma_gemm<3,2><<<dim3(2, 64), 256, SMEM_P2>>>(pFFHi, pW2Hi, pW2Lo,
        ff2_b, out, pHHi, pHLo, nullptr, NM, ND, NDFF);
}

// round 17
// speedup vs baseline: 1.3907x; 1.0153x over previous
#include <cuda_runtime.h>
#include <cuda_bf16.h>
#include <math.h>
#include <stdint.h>

#define NB 8
#define NL 1024
#define ND 256
#define NH 8
#define NDH 32
#define NDFF 2048
#define NM (NB*NL)

// ---------------- scratch (device globals; allocation-free, zero-init) ----------------
__device__ __nv_bfloat16 gQhi[64*NL*NDH];
__device__ __nv_bfloat16 gKhi[64*NL*NDH];
__device__ __nv_bfloat16 gVhi[64*NL*NDH];
__device__ __nv_bfloat16 gSrcHi[NM*ND];
__device__ __nv_bfloat16 gCtxHi[NM*ND];
__device__ __nv_bfloat16 gHHi[NM*ND], gHLo[NM*ND];
__device__ __nv_bfloat16 gFFHi[(size_t)NM*NDFF];
__device__ __nv_bfloat16 gWqkvHi[3*ND*ND];
__device__ __nv_bfloat16 gWcHi[ND*ND],   gWcLo[ND*ND];
__device__ __nv_bfloat16 gW1Hi[NDFF*ND], gW1Lo[NDFF*ND];
__device__ __nv_bfloat16 gW2Hi[ND*NDFF], gW2Lo[ND*NDFF];
__device__ float gBc[ND];
__device__ int   gLen[NB];

// ---------------- helpers ----------------
__device__ __forceinline__ uint32_t smem_u32(const void* p) {
    uint32_t a;
    asm("{ .reg .u64 t; cvta.to.shared.u64 t, %1; cvt.u32.u64 %0, t; }" : "=r"(a) : "l"(p));
    return a;
}
__device__ __forceinline__ void cpasync16(uint32_t saddr, const void* gaddr) {
    asm volatile("cp.async.cg.shared.global [%0], [%1], 16;" :: "r"(saddr), "l"(gaddr) : "memory");
}
#define CP_COMMIT() asm volatile("cp.async.commit_group;" ::: "memory")
#define CP_WAIT(n)  asm volatile("cp.async.wait_group %0;" :: "n"(n) : "memory")

#define LDSM_X4(r0, r1, r2, r3, addr) \
    asm volatile("ldmatrix.sync.aligned.m8n8.x4.shared.b16 {%0,%1,%2,%3}, [%4];" \
        : "=r"(r0), "=r"(r1), "=r"(r2), "=r"(r3) : "r"(addr))
#define LDSM_X4_T(r0, r1, r2, r3, addr) \
    asm volatile("ldmatrix.sync.aligned.m8n8.x4.trans.shared.b16 {%0,%1,%2,%3}, [%4];" \
        : "=r"(r0), "=r"(r1), "=r"(r2), "=r"(r3) : "r"(addr))

#define MMA16816(d, a, b0, b1) \
    asm volatile("mma.sync.aligned.m16n8k16.row.col.f32.bf16.bf16.f32 " \
        "{%0,%1,%2,%3}, {%4,%5,%6,%7}, {%8,%9}, {%0,%1,%2,%3};" \
        : "+f"((d)[0]), "+f"((d)[1]), "+f"((d)[2]), "+f"((d)[3]) \
        : "r"((a)[0]), "r"((a)[1]), "r"((a)[2]), "r"((a)[3]), "r"(b0), "r"(b1))

__device__ __forceinline__ float gelu_f(float x) {
    return 0.5f * x * (1.f + erff(x * 0.7071067811865475f));
}
__device__ __forceinline__ uint32_t pack2_hi(float a, float b) {
    __nv_bfloat16 h0 = __float2bfloat16(a), h1 = __float2bfloat16(b);
    return ((uint32_t)__bfloat16_as_ushort(h1) << 16) | __bfloat16_as_ushort(h0);
}
__device__ __forceinline__ uint32_t pack2_lo(float a, float b) {
    __nv_bfloat16 h0 = __float2bfloat16(a), h1 = __float2bfloat16(b);
    float l0 = a - __bfloat162float(h0), l1 = b - __bfloat162float(h1);
    __nv_bfloat16 g0 = __float2bfloat16(l0), g1 = __float2bfloat16(l1);
    return ((uint32_t)__bfloat16_as_ushort(g1) << 16) | __bfloat16_as_ushort(g0);
}

// ---------------- merged prep: setup (8 blks) + conv (3264 blks) + fuse (257 blks) ----
#define CN0 (NM*ND/4)
#define CN1 (3*ND*ND/4)
#define CN2 (NDFF*ND/4)
#define CN3 (ND*NDFF/4)
#define NCONV_BLK ((CN0+CN1+CN2+CN3)/256)   // 3264 exactly
#define NPREP_BLK (NB + NCONV_BLK + ND + 1) // 8 + 3264 + 257 = 3529

__global__ __launch_bounds__(256) void prep_kernel(
    const unsigned char* __restrict__ mb,
    const float* __restrict__ src, const float* __restrict__ w0,
    const float* __restrict__ w1,  const float* __restrict__ w2,
    const float* __restrict__ pw,  const float* __restrict__ ow,
    const float* __restrict__ ob,  const float* __restrict__ pb)
{
    const int blk = blockIdx.x, tid = threadIdx.x;
    if (blk < NB) {
        // ---- per-batch length + mask-mode detect ----
        __shared__ int flag, cnt;
        if (tid == 0) { flag = 0; cnt = 0; }
        __syncthreads();
        int f = 0;
        for (int i = tid; i < NB*NL; i += 256)
            if ((i & 3) != 0 && mb[i] != 0) f = 1;
        if (f) atomicOr(&flag, 1);
        __syncthreads();
        const int mode = flag;
        int c = 0;
        for (int i = tid; i < NL; i += 256) {
            int pad = mode ? (mb[blk*NL + i] != 0) : (((const int*)mb)[blk*NL + i] != 0);
            if (!pad) c++;
        }
        atomicAdd(&cnt, c);
        __syncthreads();
        if (tid == 0) gLen[blk] = cnt;
    } else if (blk < NB + NCONV_BLK) {
        // ---- fp32 -> bf16 conversion ----
        int i = (blk - NB) * 256 + tid;
        const float* x; __nv_bfloat16 *hi, *lo;
        if (i < CN0)                 { x = src; hi = gSrcHi;  lo = nullptr; }
        else if (i < CN0+CN1)        { i -= CN0; x = w0; hi = gWqkvHi; lo = nullptr; }
        else if (i < CN0+CN1+CN2)    { i -= CN0+CN1; x = w1; hi = gW1Hi; lo = gW1Lo; }
        else                         { i -= CN0+CN1+CN2; x = w2; hi = gW2Hi; lo = gW2Lo; }
        float4 fv = ((const float4*)x)[i];
        uint2 h;
        h.x = pack2_hi(fv.x, fv.y); h.y = pack2_hi(fv.z, fv.w);
        ((uint2*)hi)[i] = h;
        if (lo) {
            uint2 l;
            l.x = pack2_lo(fv.x, fv.y); l.y = pack2_lo(fv.z, fv.w);
            ((uint2*)lo)[i] = l;
        }
    } else {
        // ---- weight+bias fusion ----
        int i = blk - NB - NCONV_BLK, j = tid;
        if (i == ND) {
            float s = pb[j];
            #pragma unroll 8
            for (int k = 0; k < ND; k++)
                s = fmaf(pw[j*ND + k], ob[k], s);
            gBc[j] = s;
            return;
        }
        float s = 0.f;
        #pragma unroll 8
        for (int k = 0; k < ND; k++)
            s = fmaf(pw[i*ND + k], ow[k*ND + j], s);
        __nv_bfloat16 h = __float2bfloat16(s);
        gWcHi[i*ND + j] = h;
        gWcLo[i*ND + j] = __float2bfloat16(s - __bfloat162float(h));
    }
}

// ---------------- mma.sync GEMM, NPROD products, KT-wide stages ----------------
// NPROD=1/KT=64: Ah*Bh, 2-stage (QKV).   NPROD=2/KT=32: Ah*Bh + Ah*Bl, 3-stage.
// Row stride 2*KT+16 bytes (80 or 144; both odd multiples of 16 -> conflict-free ldmatrix).
#define SMEM_QKV (2 * 2 * 128 * 144)   // 73728
#define SMEM_P2  (3 * 3 * 128 * 80)    // 92160

template<int EPI, int NPROD, int KT>
__global__ __launch_bounds__(256, 2) void mma_gemm(
    const __nv_bfloat16* __restrict__ Ahi,
    const __nv_bfloat16* __restrict__ Bhi, const __nv_bfloat16* __restrict__ Blo,
    const float* __restrict__ bias,
    float* __restrict__ Cf, __nv_bfloat16* __restrict__ Chi, __nv_bfloat16* __restrict__ Clo,
    const float* __restrict__ resf, int M, int N, int K)
{
    constexpr int NMAT = NPROD + 1;
    constexpr int RS = 2 * KT + 16;         // row stride bytes
    constexpr int ATL = 128 * RS;           // one matrix tile
    constexpr int STAGE = NMAT * ATL;
    constexpr int CPR = KT / 8;             // 16B chunks per row
    constexpr int NSTAGE = (KT == 64) ? 2 : 3;

    extern __shared__ char sm[];
    const uint32_t sb = smem_u32(sm);
    const int tid = threadIdx.x;
    const int lane = tid & 31, wid = tid >> 5;
    const int wm = wid & 3, wn = wid >> 2;
    const int bm = blockIdx.y * 128, bn = blockIdx.x * 128;

    if ((bm & (NL - 1)) >= gLen[bm >> 10]) {
        if (EPI == 3) {
            const float4 z4 = make_float4(0.f, 0.f, 0.f, 0.f);
            #pragma unroll
            for (int it = 0; it < 16; it++) {
                int u = it * 256 + tid;
                int r = u >> 5, c = (u & 31) << 2;
                *(float4*)(Cf + (size_t)(bm + r) * N + bn + c) = z4;
            }
        }
        return;
    }

    float acc[2][8][4];
    #pragma unroll
    for (int i = 0; i < 2; i++)
        #pragma unroll
        for (int j = 0; j < 8; j++)
            #pragma unroll
            for (int c = 0; c < 4; c++) acc[i][j][c] = 0.f;

    const int nt = K / KT;

    auto prefetch = [&](int stage, int kt) {
        const int k0 = kt * KT;
        #pragma unroll
        for (int it = 0; it < NMAT * CPR / 2; it++) {
            int u = (it << 8) + tid;
            int mat = u / (128 * CPR);
            int w = u - mat * (128 * CPR);
            int r = w / CPR, c = w - r * CPR;
            const __nv_bfloat16* g;
            int rb;
            if (mat == 0)      { g = Ahi; rb = bm; }
            else if (mat == 1) { g = Bhi; rb = bn; }
            else               { g = Blo; rb = bn; }
            cpasync16(sb + (uint32_t)(stage * STAGE + mat * ATL + r * RS + (c << 4)),
                      g + (size_t)(rb + r) * K + k0 + (c << 3));
        }
        CP_COMMIT();
    };

    auto compute = [&](int stage) {
        const uint32_t stb = sb + (uint32_t)(stage * STAGE);
        const int g = lane >> 3;
        #pragma unroll
        for (int ks = 0; ks < KT / 16; ks++) {
            uint32_t af[2][4];
            #pragma unroll
            for (int fm = 0; fm < 2; fm++) {
                int row = wm * 32 + fm * 16 + (lane & 15);
                int chunk = ks * 2 + (lane >> 4);
                uint32_t a = stb + (uint32_t)(row * RS + chunk * 16);
                LDSM_X4(af[fm][0], af[fm][1], af[fm][2], af[fm][3], a);
            }
            uint32_t bf_[4][4];
            #pragma unroll
            for (int bp = 0; bp < NPROD; bp++) {
                #pragma unroll
                for (int fq = 0; fq < 4; fq++) {
                    int row = wn * 64 + fq * 16 + ((g >> 1) << 3) + (lane & 7);
                    int chunk = ks * 2 + (g & 1);
                    uint32_t a = stb + (uint32_t)((1 + bp) * ATL + row * RS + chunk * 16);
                    LDSM_X4(bf_[fq][0], bf_[fq][1], bf_[fq][2], bf_[fq][3], a);
                }
                #pragma unroll
                for (int fm = 0; fm < 2; fm++)
                    #pragma unroll
                    for (int fn = 0; fn < 8; fn++) {
                        uint32_t b0 = bf_[fn >> 1][(fn & 1) * 2], b1 = bf_[fn >> 1][(fn & 1) * 2 + 1];
                        MMA16816(acc[fm][fn], af[fm], b0, b1);
                    }
            }
        }
    };

    if (NSTAGE == 2) {
        prefetch(0, 0);
        for (int i = 0; i < nt; i++) {
            CP_WAIT(0);
            __syncthreads();
            if (i + 1 < nt) prefetch((i + 1) & 1, i + 1);
            compute(i & 1);
        }
    } else {
        prefetch(0, 0);
        prefetch(1, 1);
        int st = 0, stp = 2;
        for (int i = 0; i < nt; i++) {
            CP_WAIT(1);
            __syncthreads();
            if (i + 2 < nt) prefetch(stp, i + 2);
            else CP_COMMIT();
            compute(st);
            st = (st == 2) ? 0 : st + 1;
            stp = (stp == 2) ? 0 : stp + 1;
        }
    }

    const int tq = lane >> 2, tr2 = (lane & 3) << 1;
    #pragma unroll
    for (int fm = 0; fm < 2; fm++) {
        #pragma unroll
        for (int fn = 0; fn < 8; fn++) {
            int col = bn + wn * 64 + fn * 8 + tr2;
            float b0 = __ldg(bias + col), b1 = __ldg(bias + col + 1);
            #pragma unroll
            for (int half = 0; half < 2; half++) {
                int row = bm + wm * 32 + fm * 16 + tq + half * 8;
                float v0 = acc[fm][fn][half * 2]     + b0;
                float v1 = acc[fm][fn][half * 2 + 1] + b1;
                if (EPI == 0) {
                    int t = col >> 8, h = (col & 255) >> 5, dh = col & 31;
                    int bb = row >> 10, ll = row & 1023;
                    size_t o = (((size_t)(bb * NH + h)) * NL + ll) * NDH + dh;
                    uint32_t hv = pack2_hi(v0, v1);
                    if (t == 0)      *(uint32_t*)(gQhi + o) = hv;
                    else if (t == 1) *(uint32_t*)(gKhi + o) = hv;
                    else             *(uint32_t*)(gVhi + o) = hv;
                } else if (EPI == 1) {
                    size_t o = (size_t)row * N + col;
                    v0 += __ldg(resf + o); v1 += __ldg(resf + o + 1);
                    *(uint32_t*)(Chi + o) = pack2_hi(v0, v1);
                    *(uint32_t*)(Clo + o) = pack2_lo(v0, v1);
                } else if (EPI == 2) {
                    size_t o = (size_t)row * N + col;
                    v0 = gelu_f(v0); v1 = gelu_f(v1);
                    *(uint32_t*)(Chi + o) = pack2_hi(v0, v1);
                } else {
                    size_t o = (size_t)row * N + col;
                    uint32_t rh = *(const uint32_t*)(Chi + o);
                    uint32_t rl = *(const uint32_t*)(Clo + o);
                    v0 += __bfloat162float(__ushort_as_bfloat16((unsigned short)(rh & 0xffff)))
                        + __bfloat162float(__ushort_as_bfloat16((unsigned short)(rl & 0xffff)));
                    v1 += __bfloat162float(__ushort_as_bfloat16((unsigned short)(rh >> 16)))
                        + __bfloat162float(__ushort_as_bfloat16((unsigned short)(rl >> 16)));
                    int bb = row >> 10, ll = row & 1023;
                    if (ll >= gLen[bb]) { v0 = 0.f; v1 = 0.f; }
                    *(float2*)(Cf + o) = make_float2(v0, v1);
                }
            }
        }
    }
}

// ---------------- tensor-core flash attention (hi-only QK, R12 shape) ---------------
#define AQ_B 5120            // 64 rows x 80B
#define AKV_B (2*AQ_B)       // Khi + Vhi per stage

__global__ __launch_bounds__(128) void attn_mma_kernel() {
    __shared__ __align__(16) unsigned char smem[AQ_B + 2*AKV_B];
    const uint32_t sb = smem_u32(smem);
    const uint32_t sQhi = sb;
    const uint32_t sKV0 = sb + AQ_B;

    const int tid = threadIdx.x, lane = tid & 31, wq = tid >> 5;
    const int bh = blockIdx.y, b = bh >> 3, h = bh & 7;
    const int qbase = blockIdx.x * 64;
    const int g = lane >> 3;
    const int tq = lane >> 2, tt = lane & 3;

    const int S = gLen[b];
    if (qbase >= S) return;

    const __nv_bfloat16* Qh = gQhi + (size_t)bh * NL * NDH;
    const __nv_bfloat16* Kh = gKhi + (size_t)bh * NL * NDH;
    const __nv_bfloat16* Vh = gVhi + (size_t)bh * NL * NDH;

    const float LOG2E = 1.4426950408889634f;
    const float sf = (float)S;
    const float invs_l2 = LOG2E / sf;
    const float scale_l2 = 0.1767766952966369f * LOG2E;
    const int nt = (S + 63) >> 6;

    #pragma unroll
    for (int it = 0; it < 2; it++) {
        int u = (it << 7) + tid;
        int r = u >> 2, c = u & 3;
        cpasync16(sQhi + (uint32_t)(r * 80 + (c << 4)),
                  Qh + (size_t)(qbase + r) * NDH + (c << 3));
    }
    auto loadKV = [&](int stage, int kt) {
        uint32_t base = sKV0 + (uint32_t)stage * AKV_B;
        #pragma unroll
        for (int it = 0; it < 4; it++) {
            int u = (it << 7) + tid;
            int mat = u >> 8, w = u & 255, r = w >> 2, c = w & 3;
            const __nv_bfloat16* gp = (mat == 0) ? Kh : Vh;
            cpasync16(base + (uint32_t)(mat * AQ_B + r * 80 + (c << 4)),
                      gp + (size_t)(kt + r) * NDH + (c << 3));
        }
        CP_COMMIT();
    };
    loadKV(0, 0);

    uint32_t aQh[2][4];
    float oAcc[4][4];
    #pragma unroll
    for (int i = 0; i < 4; i++)
        #pragma unroll
        for (int j = 0; j < 4; j++) oAcc[i][j] = 0.f;
    float mrow0 = -1e30f, mrow1 = -1e30f, lp0 = 0.f, lp1 = 0.f;

    const float qr0 = (float)(qbase + wq * 16 + tq);
    const float qr1 = qr0 + 8.f;

    for (int i = 0; i < nt; i++) {
        if (i + 1 < nt) { loadKV((i + 1) & 1, (i + 1) << 6); CP_WAIT(1); }
        else            { CP_WAIT(0); }
        __syncthreads();

        if (i == 0) {
            #pragma unroll
            for (int ks = 0; ks < 2; ks++) {
                uint32_t roff = (uint32_t)((wq * 16 + ((g & 1) << 3) + (lane & 7)) * 80
                                           + 32 * ks + 16 * (g >> 1));
                LDSM_X4(aQh[ks][0], aQh[ks][1], aQh[ks][2], aQh[ks][3], sQhi + roff);
            }
        }

        const uint32_t sK = sKV0 + (uint32_t)(i & 1) * AKV_B;
        const uint32_t sV = sK + AQ_B;
        const int kt = i << 6;

        float sA[8][4];
        #pragma unroll
        for (int j = 0; j < 8; j++)
            #pragma unroll
            for (int c = 0; c < 4; c++) sA[j][c] = 0.f;

        #pragma unroll
        for (int ks = 0; ks < 2; ks++) {
            #pragma unroll
            for (int jp = 0; jp < 4; jp++) {
                uint32_t kh[4];
                uint32_t roff = (uint32_t)((16 * jp + ((g >> 1) << 3) + (lane & 7)) * 80
                                           + 32 * ks + 16 * (g & 1));
                LDSM_X4(kh[0], kh[1], kh[2], kh[3], sK + roff);
                MMA16816(sA[2*jp],     aQh[ks], kh[0], kh[1]);
                MMA16816(sA[2*jp + 1], aQh[ks], kh[2], kh[3]);
            }
        }

        float x[8][4];
        float tmax0 = -1e30f, tmax1 = -1e30f;
        #pragma unroll
        for (int j = 0; j < 8; j++) {
            int kc = kt + 8 * j + 2 * tt;
            float k0f = (float)kc, k1f = k0f + 1.f;
            float b00 = (kc     < S) ? LOG2E - fabsf(qr0 - k0f) * invs_l2 : -1e30f;
            float b01 = (kc + 1 < S) ? LOG2E - fabsf(qr0 - k1f) * invs_l2 : -1e30f;
            float b10 = (kc     < S) ? LOG2E - fabsf(qr1 - k0f) * invs_l2 : -1e30f;
            float b11 = (kc + 1 < S) ? LOG2E - fabsf(qr1 - k1f) * invs_l2 : -1e30f;
            x[j][0] = fmaf(sA[j][0], scale_l2, b00);
            x[j][1] = fmaf(sA[j][1], scale_l2, b01);
            x[j][2] = fmaf(sA[j][2], scale_l2, b10);
            x[j][3] = fmaf(sA[j][3], scale_l2, b11);
            tmax0 = fmaxf(tmax0, fmaxf(x[j][0], x[j][1]));
            tmax1 = fmaxf(tmax1, fmaxf(x[j][2], x[j][3]));
        }
        tmax0 = fmaxf(tmax0, __shfl_xor_sync(0xffffffff, tmax0, 1));
        tmax0 = fmaxf(tmax0, __shfl_xor_sync(0xffffffff, tmax0, 2));
        tmax1 = fmaxf(tmax1, __shfl_xor_sync(0xffffffff, tmax1, 1));
        tmax1 = fmaxf(tmax1, __shfl_xor_sync(0xffffffff, tmax1, 2));
        float mn0 = fmaxf(mrow0, tmax0), mn1 = fmaxf(mrow1, tmax1);
        float corr0 = exp2f(mrow0 - mn0), corr1 = exp2f(mrow1 - mn1);
        mrow0 = mn0; mrow1 = mn1;
        lp0 *= corr0; lp1 *= corr1;
        #pragma unroll
        for (int nf = 0; nf < 4; nf++) {
            oAcc[nf][0] *= corr0; oAcc[nf][1] *= corr0;
            oAcc[nf][2] *= corr1; oAcc[nf][3] *= corr1;
        }

        uint32_t aP[4][4];
        #pragma unroll
        for (int j = 0; j < 8; j++) {
            float p0 = exp2f(x[j][0] - mn0), p1 = exp2f(x[j][1] - mn0);
            float p2 = exp2f(x[j][2] - mn1), p3 = exp2f(x[j][3] - mn1);
            lp0 += p0 + p1; lp1 += p2 + p3;
            int jp = j >> 1, s2 = (j & 1) << 1;
            aP[jp][s2]     = pack2_hi(p0, p1);
            aP[jp][s2 + 1] = pack2_hi(p2, p3);
        }

        #pragma unroll
        for (int jp = 0; jp < 4; jp++) {
            uint32_t bv[8];
            uint32_t roff = (uint32_t)((16 * jp + ((g & 1) << 3) + (lane & 7)) * 80
                                       + 16 * (g >> 1));
            LDSM_X4_T(bv[0], bv[1], bv[2], bv[3], sV + roff);
            LDSM_X4_T(bv[4], bv[5], bv[6], bv[7], sV + roff + 32);
            MMA16816(oAcc[0], aP[jp], bv[0], bv[1]);
            MMA16816(oAcc[1], aP[jp], bv[2], bv[3]);
            MMA16816(oAcc[2], aP[jp], bv[4], bv[5]);
            MMA16816(oAcc[3], aP[jp], bv[6], bv[7]);
        }
        __syncthreads();
    }

    lp0 += __shfl_xor_sync(0xffffffff, lp0, 1);
    lp0 += __shfl_xor_sync(0xffffffff, lp0, 2);
    lp1 += __shfl_xor_sync(0xffffffff, lp1, 1);
    lp1 += __shfl_xor_sync(0xffffffff, lp1, 2);
    float inv0 = 1.f / lp0, inv1 = 1.f / lp1;
    int r0 = qbase + wq * 16 + tq, r1 = r0 + 8;
    #pragma unroll
    for (int nf = 0; nf < 4; nf++) {
        int dh = 8 * nf + 2 * tt;
        size_t o0 = ((size_t)(b * NL + r0)) * ND + h * NDH + dh;
        size_t o1 = ((size_t)(b * NL + r1)) * ND + h * NDH + dh;
        *(uint32_t*)(gCtxHi + o0) = pack2_hi(oAcc[nf][0] * inv0, oAcc[nf][1] * inv0);
        *(uint32_t*)(gCtxHi + o1) = pack2_hi(oAcc[nf][2] * inv1, oAcc[nf][3] * inv1);
    }
}

// ---------------- launcher ----------------
extern "C" void kernel_launch(void* const* d_in, const int* in_sizes, int n_in,
                              void* d_out, int out_size) {
    const float* src       = (const float*)d_in[0];
    const unsigned char* mask = (const unsigned char*)d_in[1];
    const float* in_proj_w = (const float*)d_in[2];
    const float* in_proj_b = (const float*)d_in[3];
    const float* out_w     = (const float*)d_in[4];
    const float* out_b     = (const float*)d_in[5];
    const float* proj_w    = (const float*)d_in[6];
    const float* proj_b    = (const float*)d_in[7];
    const float* ff1_w     = (const float*)d_in[8];
    const float* ff1_b     = (const float*)d_in[9];
    const float* ff2_w     = (const float*)d_in[10];
    const float* ff2_b     = (const float*)d_in[11];
    float* out = (float*)d_out;

    cudaFuncSetAttribute((void*)mma_gemm<0,1,64>, cudaFuncAttributeMaxDynamicSharedMemorySize, SMEM_QKV);
    cudaFuncSetAttribute((void*)mma_gemm<1,2,32>, cudaFuncAttributeMaxDynamicSharedMemorySize, SMEM_P2);
    cudaFuncSetAttribute((void*)mma_gemm<2,2,32>, cudaFuncAttributeMaxDynamicSharedMemorySize, SMEM_P2);
    cudaFuncSetAttribute((void*)mma_gemm<3,2,32>, cudaFuncAttributeMaxDynamicSharedMemorySize, SMEM_P2);

    float *pBc;
    __nv_bfloat16 *pSrcHi, *pCtxHi, *pHHi, *pHLo, *pFFHi;
    __nv_bfloat16 *pWqkvHi, *pWcHi, *pWcLo, *pW1Hi, *pW1Lo, *pW2Hi, *pW2Lo;
    cudaGetSymbolAddress((void**)&pBc, gBc);
    cudaGetSymbolAddress((void**)&pSrcHi, gSrcHi);
    cudaGetSymbolAddress((void**)&pCtxHi, gCtxHi);
    cudaGetSymbolAddress((void**)&pHHi, gHHi);   cudaGetSymbolAddress((void**)&pHLo, gHLo);
    cudaGetSymbolAddress((void**)&pFFHi, gFFHi);
    cudaGetSymbolAddress((void**)&pWqkvHi, gWqkvHi);
    cudaGetSymbolAddress((void**)&pWcHi, gWcHi); cudaGetSymbolAddress((void**)&pWcLo, gWcLo);
    cudaGetSymbolAddress((void**)&pW1Hi, gW1Hi); cudaGetSymbolAddress((void**)&pW1Lo, gW1Lo);
    cudaGetSymbolAddress((void**)&pW2Hi, gW2Hi); cudaGetSymbolAddress((void**)&pW2Lo, gW2Lo);

    // single merged prep launch (setup + conversions + weight fusion)
    prep_kernel<<<NPREP_BLK, 256>>>(mask, src, in_proj_w, ff1_w, ff2_w,
                                    proj_w, out_w, out_b, proj_b);

    // QKV = src @ in_proj_w^T + b (1 product, K=64 stages) -> bf16 Q/K/V
    mma_gemm<0,1,64><<<dim3(6, 64), 256, SMEM_QKV>>>(pSrcHi, pWqkvHi, nullptr,
        in_proj_b, nullptr, nullptr, nullptr, nullptr, NM, 3*ND, ND);
    // tensor-core attention -> ctx hi
    attn_mma_kernel<<<dim3(16, 64), 128>>>();
    // H = src + ctx_h @ (Wc_h + Wc_l)^T + bc -> hi/lo
    mma_gemm<1,2,32><<<dim3(2, 64), 256, SMEM_P2>>>(pCtxHi, pWcHi, pWcLo,
        pBc, nullptr, pHHi, pHLo, src, NM, ND, ND);
    // ff = gelu(H_h @ (W1_h + W1_l)^T + b1) -> hi only
    mma_gemm<2,2,32><<<dim3(16, 64), 256, SMEM_P2>>>(pHHi, pW1Hi, pW1Lo,
        ff1_b, nullptr, pFFHi, nullptr, nullptr, NM, NDFF, ND);
    // out = (Hhi+Hlo) + ff_h @ (W2_h + W2_l)^T + b2, padded rows zeroed
    mma_gemm<3,2,32><<<dim3(2, 64), 256, SMEM_P2>>>(pFFHi, pW2Hi, pW2Lo,
        ff2_b, out, pHHi, pHLo, nullptr, NM, ND, NDFF);
}